// round 1
// baseline (speedup 1.0000x reference)
#include <cuda_runtime.h>
#include <math.h>

#define BB 4
#define SS 1024
#define DD 1024
#define HH 16
#define HD 64
#define BS (BB*SS)     /* 4096 */
#define DFF (4*DD)     /* 4096 */
#define NBH (BB*HH)    /* 64 */

// ---------------- scratch (static __device__, no allocations) ----------------
__device__ float g_h  [BS*DD];
__device__ float g_q  [BS*DD];
__device__ float g_k  [BS*DD];
__device__ float g_v  [BS*DD];
__device__ float g_sc [NBH*SS*SS];   // 256 MB scores
__device__ float g_ctx[BS*DD];
__device__ float g_x2 [BS*DD];
__device__ float g_h2 [BS*DD];
__device__ float g_mid[BS*DFF];      // 64 MB

// ---------------- layernorm: one block per row ----------------
__global__ void ln_kernel(const float* __restrict__ x,
                          const float* __restrict__ scale,
                          const float* __restrict__ shift,
                          float* __restrict__ out)
{
    int row = blockIdx.x;
    const float* xr = x + (size_t)row * DD;
    float* orow = out + (size_t)row * DD;
    __shared__ float red[256];
    int t = threadIdx.x;

    float s = 0.f;
    for (int i = t; i < DD; i += 256) s += xr[i];
    red[t] = s; __syncthreads();
    for (int o = 128; o > 0; o >>= 1) { if (t < o) red[t] += red[t + o]; __syncthreads(); }
    float mean = red[0] * (1.0f / DD);
    __syncthreads();

    float v = 0.f;
    for (int i = t; i < DD; i += 256) { float d = xr[i] - mean; v += d * d; }
    red[t] = v; __syncthreads();
    for (int o = 128; o > 0; o >>= 1) { if (t < o) red[t] += red[t + o]; __syncthreads(); }
    float rstd = rsqrtf(red[0] * (1.0f / DD) + 1e-5f);

    for (int i = t; i < DD; i += 256)
        orow[i] = scale[i] * (xr[i] - mean) * rstd + shift[i];
}

// ---------------- generic 128x128x8 SGEMM (NN), fused epilogue ----------------
// C[M,N] = A[M,K] @ B[K,N] (+bias[N]) (gelu?) (+res[M,N])
__global__ __launch_bounds__(256, 2)
void gemm128_nn(const float* __restrict__ A, const float* __restrict__ Bm,
                float* __restrict__ C, int M, int N, int K,
                const float* __restrict__ bias,
                const float* __restrict__ res,
                int gelu)
{
    __shared__ float As[8][128];
    __shared__ float Bs[8][128];
    int bx = blockIdx.x, by = blockIdx.y;
    int tid = threadIdx.x;
    int tx = tid & 15, ty = tid >> 4;

    const float* Ab = A + (size_t)by * 128 * K;
    const float* Bb = Bm + bx * 128;

    int arow = tid >> 1, ak4 = (tid & 1) * 4;
    int brow = tid >> 5, bcol4 = (tid & 31) * 4;

    float acc[8][8];
    #pragma unroll
    for (int i = 0; i < 8; i++)
        #pragma unroll
        for (int j = 0; j < 8; j++) acc[i][j] = 0.f;

    for (int k0 = 0; k0 < K; k0 += 8) {
        float4 av = *reinterpret_cast<const float4*>(Ab + (size_t)arow * K + k0 + ak4);
        As[ak4 + 0][arow] = av.x; As[ak4 + 1][arow] = av.y;
        As[ak4 + 2][arow] = av.z; As[ak4 + 3][arow] = av.w;
        float4 bv = *reinterpret_cast<const float4*>(Bb + (size_t)(k0 + brow) * N + bcol4);
        *reinterpret_cast<float4*>(&Bs[brow][bcol4]) = bv;
        __syncthreads();
        #pragma unroll
        for (int kk = 0; kk < 8; kk++) {
            float a[8], b[8];
            *(float4*)&a[0] = *(float4*)&As[kk][ty * 8];
            *(float4*)&a[4] = *(float4*)&As[kk][ty * 8 + 4];
            *(float4*)&b[0] = *(float4*)&Bs[kk][tx * 8];
            *(float4*)&b[4] = *(float4*)&Bs[kk][tx * 8 + 4];
            #pragma unroll
            for (int i = 0; i < 8; i++)
                #pragma unroll
                for (int j = 0; j < 8; j++)
                    acc[i][j] += a[i] * b[j];
        }
        __syncthreads();
    }

    int m0 = by * 128 + ty * 8;
    int n0 = bx * 128 + tx * 8;
    for (int i = 0; i < 8; i++) {
        size_t rowoff = (size_t)(m0 + i) * N;
        #pragma unroll
        for (int j = 0; j < 8; j++) {
            float c = acc[i][j];
            int n = n0 + j;
            if (bias) c += bias[n];
            if (gelu) {
                float xx = c;
                float tv = 0.7978845608028654f * (xx + 0.044715f * xx * xx * xx);
                c = 0.5f * xx * (1.0f + tanhf(tv));
            }
            if (res) c += res[rowoff + n];
            C[rowoff + n] = c;
        }
    }
}

// ---------------- scores: per (b,h) 64x64 tiles of Q K^T, causal skip ----------------
__global__ void scores_kernel(const float* __restrict__ q, const float* __restrict__ k,
                              const int* __restrict__ amask)
{
    int z = blockIdx.z;               // b*H + h
    int b = z / HH, h = z % HH;
    int row0 = blockIdx.y * 64, col0 = blockIdx.x * 64;
    float* out = g_sc + (size_t)z * SS * SS;
    int tid = threadIdx.x;

    if (col0 > row0 + 63) {           // fully above causal diagonal
        for (int i = 0; i < 16; i++) {
            int idx = tid + i * 256;
            int r = idx >> 6, c = idx & 63;
            out[(size_t)(row0 + r) * SS + col0 + c] = -INFINITY;
        }
        return;
    }

    const float* qb = q + ((size_t)b * SS + row0) * DD + h * HD;
    const float* kb = k + ((size_t)b * SS + col0) * DD + h * HD;
    __shared__ float Qs[HD][65];      // [d][m]
    __shared__ float Ks[HD][65];      // [d][n]
    for (int i = 0; i < 16; i++) {
        int idx = tid + i * 256;
        int r = idx >> 6, d = idx & 63;
        Qs[d][r] = qb[(size_t)r * DD + d];
        Ks[d][r] = kb[(size_t)r * DD + d];
    }
    __syncthreads();

    int tx = tid & 15, ty = tid >> 4;
    float acc[4][4];
    #pragma unroll
    for (int i = 0; i < 4; i++)
        #pragma unroll
        for (int j = 0; j < 4; j++) acc[i][j] = 0.f;

    for (int d = 0; d < HD; d++) {
        float a[4], b4[4];
        #pragma unroll
        for (int i = 0; i < 4; i++) a[i] = Qs[d][ty * 4 + i];
        #pragma unroll
        for (int j = 0; j < 4; j++) b4[j] = Ks[d][tx * 4 + j];
        #pragma unroll
        for (int i = 0; i < 4; i++)
            #pragma unroll
            for (int j = 0; j < 4; j++)
                acc[i][j] += a[i] * b4[j];
    }

    for (int i = 0; i < 4; i++) {
        int r = row0 + ty * 4 + i;
        for (int j = 0; j < 4; j++) {
            int c = col0 + tx * 4 + j;
            float v = acc[i][j] * 0.125f;  // 1/sqrt(64)
            if (c > r || amask[b * SS + c] == 0) v = -INFINITY;
            out[(size_t)r * SS + c] = v;
        }
    }
}

// ---------------- softmax: one block per score row ----------------
__global__ void softmax_kernel()
{
    size_t row = blockIdx.x;
    float* p = g_sc + row * SS;
    __shared__ float red[256];
    int t = threadIdx.x;

    float m = -INFINITY;
    for (int i = t; i < SS; i += 256) m = fmaxf(m, p[i]);
    red[t] = m; __syncthreads();
    for (int o = 128; o > 0; o >>= 1) { if (t < o) red[t] = fmaxf(red[t], red[t + o]); __syncthreads(); }
    m = red[0]; __syncthreads();

    float s = 0.f;
    for (int i = t; i < SS; i += 256) { float e = __expf(p[i] - m); p[i] = e; s += e; }
    red[t] = s; __syncthreads();
    for (int o = 128; o > 0; o >>= 1) { if (t < o) red[t] += red[t + o]; __syncthreads(); }
    float inv = 1.0f / red[0];

    for (int i = t; i < SS; i += 256) p[i] *= inv;
}

// ---------------- ctx = P @ V per (b,h); skip causal-zero K tiles ----------------
__global__ void ctx_kernel(const float* __restrict__ v)
{
    int z = blockIdx.z, b = z / HH, h = z % HH;
    int row0 = blockIdx.y * 64;
    const float* P = g_sc + (size_t)z * SS * SS;
    const float* vb = v + (size_t)b * SS * DD + h * HD;
    float* ob = g_ctx + (size_t)b * SS * DD + h * HD;
    int tid = threadIdx.x;
    int tx = tid & 15, ty = tid >> 4;

    __shared__ float Ps[16][65];   // [kk][m] transposed
    __shared__ float Vs[16][64];   // [kk][n]
    float acc[4][4];
    #pragma unroll
    for (int i = 0; i < 4; i++)
        #pragma unroll
        for (int j = 0; j < 4; j++) acc[i][j] = 0.f;

    int m = tid >> 2, kk4 = (tid & 3) * 4;
    int kv = tid >> 4, n4 = (tid & 15) * 4;
    int kmax = row0 + 64;          // P[i][k]==0 for k > i (causal)

    for (int k0 = 0; k0 < kmax; k0 += 16) {
        const float* pr = P + (size_t)(row0 + m) * SS + k0 + kk4;
        Ps[kk4 + 0][m] = pr[0]; Ps[kk4 + 1][m] = pr[1];
        Ps[kk4 + 2][m] = pr[2]; Ps[kk4 + 3][m] = pr[3];
        *(float4*)&Vs[kv][n4] = *(const float4*)(vb + (size_t)(k0 + kv) * DD + n4);
        __syncthreads();
        #pragma unroll
        for (int kk = 0; kk < 16; kk++) {
            float a[4], b4[4];
            #pragma unroll
            for (int i = 0; i < 4; i++) a[i] = Ps[kk][ty * 4 + i];
            *(float4*)&b4[0] = *(float4*)&Vs[kk][tx * 4];
            #pragma unroll
            for (int i = 0; i < 4; i++)
                #pragma unroll
                for (int j = 0; j < 4; j++)
                    acc[i][j] += a[i] * b4[j];
        }
        __syncthreads();
    }

    for (int i = 0; i < 4; i++)
        for (int j = 0; j < 4; j++)
            ob[(size_t)(row0 + ty * 4 + i) * DD + tx * 4 + j] = acc[i][j];
}

// ---------------- host launch ----------------
extern "C" void kernel_launch(void* const* d_in, const int* in_sizes, int n_in,
                              void* d_out, int out_size)
{
    const float* x     = (const float*)d_in[0];
    const int*   amask = (const int*)  d_in[1];
    const float* wq    = (const float*)d_in[2];
    const float* wk    = (const float*)d_in[3];
    const float* wv    = (const float*)d_in[4];
    const float* wo    = (const float*)d_in[5];
    const float* bo    = (const float*)d_in[6];
    const float* ln1s  = (const float*)d_in[7];
    const float* ln1b  = (const float*)d_in[8];
    const float* ln2s  = (const float*)d_in[9];
    const float* ln2b  = (const float*)d_in[10];
    const float* w1    = (const float*)d_in[11];
    const float* b1    = (const float*)d_in[12];
    const float* w2    = (const float*)d_in[13];
    const float* b2    = (const float*)d_in[14];
    float* out = (float*)d_out;

    float *h, *q, *k, *v, *ctx, *x2, *h2, *mid;
    cudaGetSymbolAddress((void**)&h,   g_h);
    cudaGetSymbolAddress((void**)&q,   g_q);
    cudaGetSymbolAddress((void**)&k,   g_k);
    cudaGetSymbolAddress((void**)&v,   g_v);
    cudaGetSymbolAddress((void**)&ctx, g_ctx);
    cudaGetSymbolAddress((void**)&x2,  g_x2);
    cudaGetSymbolAddress((void**)&h2,  g_h2);
    cudaGetSymbolAddress((void**)&mid, g_mid);

    // LN1
    ln_kernel<<<BS, 256>>>(x, ln1s, ln1b, h);

    // Q, K, V projections
    dim3 gQKV(DD / 128, BS / 128);
    gemm128_nn<<<gQKV, 256>>>(h, wq, q, BS, DD, DD, nullptr, nullptr, 0);
    gemm128_nn<<<gQKV, 256>>>(h, wk, k, BS, DD, DD, nullptr, nullptr, 0);
    gemm128_nn<<<gQKV, 256>>>(h, wv, v, BS, DD, DD, nullptr, nullptr, 0);

    // attention
    scores_kernel<<<dim3(SS / 64, SS / 64, NBH), 256>>>(q, k, amask);
    softmax_kernel<<<NBH * SS, 256>>>();
    ctx_kernel<<<dim3(1, SS / 64, NBH), 256>>>(v);

    // output projection + residual
    gemm128_nn<<<gQKV, 256>>>(ctx, wo, x2, BS, DD, DD, bo, x, 0);

    // LN2 + FFN
    ln_kernel<<<BS, 256>>>(x2, ln2s, ln2b, h2);
    gemm128_nn<<<dim3(DFF / 128, BS / 128), 256>>>(h2, w1, mid, BS, DFF, DD, b1, nullptr, 1);
    gemm128_nn<<<dim3(DD / 128, BS / 128), 256>>>(mid, w2, out, BS, DD, DFF, b2, x2, 0);
}

// round 2
// speedup vs baseline: 5.1126x; 5.1126x over previous
#include <cuda_runtime.h>
#include <math.h>
#include <stdint.h>

#define BB 4
#define SS 1024
#define DD 1024
#define HH 16
#define HD 64
#define BS (BB*SS)     /* 4096 */
#define DFF (4*DD)     /* 4096 */
#define NBH (BB*HH)    /* 64 */

// ---------------- scratch (static __device__, no allocations) ----------------
__device__ float g_h  [BS*DD];
__device__ float g_q  [BS*DD];
__device__ float g_k  [BS*DD];
__device__ float g_v  [BS*DD];
__device__ float g_sc [NBH*SS*SS];   // 256 MB scores
__device__ float g_ctx[BS*DD];
__device__ float g_x2 [BS*DD];
__device__ float g_h2 [BS*DD];
__device__ float g_mid[BS*DFF];      // 64 MB

// ---------------- helpers ----------------
__device__ __forceinline__ uint32_t f2tf(float x) {
    uint32_t r;
    asm("cvt.rna.tf32.f32 %0, %1;" : "=r"(r) : "f"(x));
    return r;
}

__device__ __forceinline__ float gelu_f(float x) {
    float t = 0.7978845608028654f * (x + 0.044715f * x * x * x);
    return 0.5f * x * (1.0f + tanhf(t));
}

// ---------------- layernorm: one block per row ----------------
__global__ void ln_kernel(const float* __restrict__ x,
                          const float* __restrict__ scale,
                          const float* __restrict__ shift,
                          float* __restrict__ out)
{
    int row = blockIdx.x;
    const float* xr = x + (size_t)row * DD;
    float* orow = out + (size_t)row * DD;
    __shared__ float red[256];
    int t = threadIdx.x;

    float s = 0.f;
    for (int i = t; i < DD; i += 256) s += xr[i];
    red[t] = s; __syncthreads();
    for (int o = 128; o > 0; o >>= 1) { if (t < o) red[t] += red[t + o]; __syncthreads(); }
    float mean = red[0] * (1.0f / DD);
    __syncthreads();

    float v = 0.f;
    for (int i = t; i < DD; i += 256) { float d = xr[i] - mean; v += d * d; }
    red[t] = v; __syncthreads();
    for (int o = 128; o > 0; o >>= 1) { if (t < o) red[t] += red[t + o]; __syncthreads(); }
    float rstd = rsqrtf(red[0] * (1.0f / DD) + 1e-5f);

    for (int i = t; i < DD; i += 256)
        orow[i] = scale[i] * (xr[i] - mean) * rstd + shift[i];
}

// ---------------- tf32 tensor-core SGEMM: 128x128x16 tile, mma.m16n8k8 ----------------
// C[M,N] = A[M,K] @ B[K,N] (+bias[N]) (gelu?) (+res[M,N])
// M,N multiples of 128; K multiple of 16.
__global__ __launch_bounds__(256, 2)
void gemm_tf32(const float* __restrict__ A, const float* __restrict__ Bm,
               float* __restrict__ C, int M, int N, int K,
               const float* __restrict__ bias,
               const float* __restrict__ res,
               int gelu)
{
    __shared__ uint32_t As[16][136];   // [k][m], stride 136 -> conflict-free frag LDS
    __shared__ uint32_t Bs[16][136];   // [k][n]

    const int tid  = threadIdx.x;
    const int lane = tid & 31;
    const int warp = tid >> 5;
    const int g    = lane >> 2;        // 0..7
    const int tig  = lane & 3;         // 0..3
    const int mw   = (warp >> 2) * 64; // warp row origin in tile
    const int nw   = (warp & 3) * 32;  // warp col origin in tile
    const int bx = blockIdx.x, by = blockIdx.y;

    // A loader: 128 rows x 16 cols; thread covers rows (tid>>2) and (tid>>2)+64, cols (tid&3)*4..+3
    const int ar  = tid >> 2;          // 0..63
    const int akc = (tid & 3) * 4;     // 0,4,8,12
    const float* Aptr = A + (size_t)(by * 128 + ar) * K + akc;

    // B loader: 16 rows x 128 cols; thread covers rows (tid>>5), (tid>>5)+8, cols (tid&31)*4..+3
    const int br = tid >> 5;           // 0..7
    const int bc = (tid & 31) * 4;     // 0..124
    const float* Bptr = Bm + (size_t)br * N + bx * 128 + bc;

    float4 ra0, ra1, rb0, rb1;
    ra0 = *(const float4*)(Aptr);
    ra1 = *(const float4*)(Aptr + (size_t)64 * K);
    rb0 = *(const float4*)(Bptr);
    rb1 = *(const float4*)(Bptr + (size_t)8 * N);

    float acc[4][4][4];
    #pragma unroll
    for (int i = 0; i < 4; i++)
        #pragma unroll
        for (int j = 0; j < 4; j++)
            #pragma unroll
            for (int c = 0; c < 4; c++) acc[i][j][c] = 0.f;

    for (int k0 = 0; k0 < K; k0 += 16) {
        // commit staged tiles to smem (tf32-converted)
        As[akc + 0][ar] = f2tf(ra0.x);
        As[akc + 1][ar] = f2tf(ra0.y);
        As[akc + 2][ar] = f2tf(ra0.z);
        As[akc + 3][ar] = f2tf(ra0.w);
        As[akc + 0][ar + 64] = f2tf(ra1.x);
        As[akc + 1][ar + 64] = f2tf(ra1.y);
        As[akc + 2][ar + 64] = f2tf(ra1.z);
        As[akc + 3][ar + 64] = f2tf(ra1.w);
        *(uint4*)&Bs[br][bc]     = make_uint4(f2tf(rb0.x), f2tf(rb0.y), f2tf(rb0.z), f2tf(rb0.w));
        *(uint4*)&Bs[br + 8][bc] = make_uint4(f2tf(rb1.x), f2tf(rb1.y), f2tf(rb1.z), f2tf(rb1.w));
        __syncthreads();

        // prefetch next tile (latency hidden behind mma work)
        if (k0 + 16 < K) {
            ra0 = *(const float4*)(Aptr + (k0 + 16));
            ra1 = *(const float4*)(Aptr + (size_t)64 * K + (k0 + 16));
            rb0 = *(const float4*)(Bptr + (size_t)(k0 + 16) * N);
            rb1 = *(const float4*)(Bptr + (size_t)(k0 + 24) * N);
        }

        #pragma unroll
        for (int kb = 0; kb < 16; kb += 8) {
            uint32_t a[4][4], b[4][2];
            #pragma unroll
            for (int i = 0; i < 4; i++) {
                int m = mw + i * 16 + g;
                a[i][0] = As[kb + tig][m];
                a[i][1] = As[kb + tig][m + 8];
                a[i][2] = As[kb + tig + 4][m];
                a[i][3] = As[kb + tig + 4][m + 8];
            }
            #pragma unroll
            for (int j = 0; j < 4; j++) {
                int n = nw + j * 8 + g;
                b[j][0] = Bs[kb + tig][n];
                b[j][1] = Bs[kb + tig + 4][n];
            }
            #pragma unroll
            for (int i = 0; i < 4; i++)
                #pragma unroll
                for (int j = 0; j < 4; j++) {
                    asm volatile(
                        "mma.sync.aligned.m16n8k8.row.col.f32.tf32.tf32.f32 "
                        "{%0,%1,%2,%3}, {%4,%5,%6,%7}, {%8,%9}, {%0,%1,%2,%3};"
                        : "+f"(acc[i][j][0]), "+f"(acc[i][j][1]),
                          "+f"(acc[i][j][2]), "+f"(acc[i][j][3])
                        : "r"(a[i][0]), "r"(a[i][1]), "r"(a[i][2]), "r"(a[i][3]),
                          "r"(b[j][0]), "r"(b[j][1]));
                }
        }
        __syncthreads();
    }

    // epilogue: c0,c1 -> (row, col..col+1); c2,c3 -> (row+8, col..col+1)
    #pragma unroll
    for (int i = 0; i < 4; i++) {
        int row = by * 128 + mw + i * 16 + g;
        #pragma unroll
        for (int j = 0; j < 4; j++) {
            int col = bx * 128 + nw + j * 8 + tig * 2;
            float v0 = acc[i][j][0], v1 = acc[i][j][1];
            float v2 = acc[i][j][2], v3 = acc[i][j][3];
            if (bias) {
                float b0 = bias[col], b1 = bias[col + 1];
                v0 += b0; v1 += b1; v2 += b0; v3 += b1;
            }
            if (gelu) { v0 = gelu_f(v0); v1 = gelu_f(v1); v2 = gelu_f(v2); v3 = gelu_f(v3); }
            size_t o0 = (size_t)row * N + col;
            size_t o1 = (size_t)(row + 8) * N + col;
            if (res) {
                v0 += res[o0]; v1 += res[o0 + 1];
                v2 += res[o1]; v3 += res[o1 + 1];
            }
            C[o0] = v0; C[o0 + 1] = v1;
            C[o1] = v2; C[o1 + 1] = v3;
        }
    }
}

// ---------------- scores: per (b,h) 64x64 tiles of Q K^T, causal skip ----------------
__global__ void scores_kernel(const float* __restrict__ q, const float* __restrict__ k,
                              const int* __restrict__ amask)
{
    int z = blockIdx.z;               // b*H + h
    int b = z / HH, h = z % HH;
    int row0 = blockIdx.y * 64, col0 = blockIdx.x * 64;
    float* out = g_sc + (size_t)z * SS * SS;
    int tid = threadIdx.x;

    if (col0 > row0 + 63) {           // fully above causal diagonal
        for (int i = 0; i < 16; i++) {
            int idx = tid + i * 256;
            int r = idx >> 6, c = idx & 63;
            out[(size_t)(row0 + r) * SS + col0 + c] = -INFINITY;
        }
        return;
    }

    const float* qb = q + ((size_t)b * SS + row0) * DD + h * HD;
    const float* kb = k + ((size_t)b * SS + col0) * DD + h * HD;
    __shared__ float Qs[HD][65];      // [d][m]
    __shared__ float Ks[HD][65];      // [d][n]
    for (int i = 0; i < 16; i++) {
        int idx = tid + i * 256;
        int r = idx >> 6, d = idx & 63;
        Qs[d][r] = qb[(size_t)r * DD + d];
        Ks[d][r] = kb[(size_t)r * DD + d];
    }
    __syncthreads();

    int tx = tid & 15, ty = tid >> 4;
    float acc[4][4];
    #pragma unroll
    for (int i = 0; i < 4; i++)
        #pragma unroll
        for (int j = 0; j < 4; j++) acc[i][j] = 0.f;

    for (int d = 0; d < HD; d++) {
        float a[4], b4[4];
        #pragma unroll
        for (int i = 0; i < 4; i++) a[i] = Qs[d][ty * 4 + i];
        #pragma unroll
        for (int j = 0; j < 4; j++) b4[j] = Ks[d][tx * 4 + j];
        #pragma unroll
        for (int i = 0; i < 4; i++)
            #pragma unroll
            for (int j = 0; j < 4; j++)
                acc[i][j] += a[i] * b4[j];
    }

    for (int i = 0; i < 4; i++) {
        int r = row0 + ty * 4 + i;
        for (int j = 0; j < 4; j++) {
            int c = col0 + tx * 4 + j;
            float v = acc[i][j] * 0.125f;  // 1/sqrt(64)
            if (c > r || amask[b * SS + c] == 0) v = -INFINITY;
            out[(size_t)r * SS + c] = v;
        }
    }
}

// ---------------- softmax: one block per score row ----------------
__global__ void softmax_kernel()
{
    size_t row = blockIdx.x;
    float* p = g_sc + row * SS;
    __shared__ float red[256];
    int t = threadIdx.x;

    float m = -INFINITY;
    for (int i = t; i < SS; i += 256) m = fmaxf(m, p[i]);
    red[t] = m; __syncthreads();
    for (int o = 128; o > 0; o >>= 1) { if (t < o) red[t] = fmaxf(red[t], red[t + o]); __syncthreads(); }
    m = red[0]; __syncthreads();

    float s = 0.f;
    for (int i = t; i < SS; i += 256) { float e = __expf(p[i] - m); p[i] = e; s += e; }
    red[t] = s; __syncthreads();
    for (int o = 128; o > 0; o >>= 1) { if (t < o) red[t] += red[t + o]; __syncthreads(); }
    float inv = 1.0f / red[0];

    for (int i = t; i < SS; i += 256) p[i] *= inv;
}

// ---------------- ctx = P @ V per (b,h); skip causal-zero K tiles ----------------
__global__ void ctx_kernel(const float* __restrict__ v)
{
    int z = blockIdx.z, b = z / HH, h = z % HH;
    int row0 = blockIdx.y * 64;
    const float* P = g_sc + (size_t)z * SS * SS;
    const float* vb = v + (size_t)b * SS * DD + h * HD;
    float* ob = g_ctx + (size_t)b * SS * DD + h * HD;
    int tid = threadIdx.x;
    int tx = tid & 15, ty = tid >> 4;

    __shared__ float Ps[16][65];   // [kk][m] transposed
    __shared__ float Vs[16][64];   // [kk][n]
    float acc[4][4];
    #pragma unroll
    for (int i = 0; i < 4; i++)
        #pragma unroll
        for (int j = 0; j < 4; j++) acc[i][j] = 0.f;

    int m = tid >> 2, kk4 = (tid & 3) * 4;
    int kv = tid >> 4, n4 = (tid & 15) * 4;
    int kmax = row0 + 64;          // P[i][k]==0 for k > i (causal)

    for (int k0 = 0; k0 < kmax; k0 += 16) {
        const float* pr = P + (size_t)(row0 + m) * SS + k0 + kk4;
        Ps[kk4 + 0][m] = pr[0]; Ps[kk4 + 1][m] = pr[1];
        Ps[kk4 + 2][m] = pr[2]; Ps[kk4 + 3][m] = pr[3];
        *(float4*)&Vs[kv][n4] = *(const float4*)(vb + (size_t)(k0 + kv) * DD + n4);
        __syncthreads();
        #pragma unroll
        for (int kk = 0; kk < 16; kk++) {
            float a[4], b4[4];
            #pragma unroll
            for (int i = 0; i < 4; i++) a[i] = Ps[kk][ty * 4 + i];
            *(float4*)&b4[0] = *(float4*)&Vs[kk][tx * 4];
            #pragma unroll
            for (int i = 0; i < 4; i++)
                #pragma unroll
                for (int j = 0; j < 4; j++)
                    acc[i][j] += a[i] * b4[j];
        }
        __syncthreads();
    }

    for (int i = 0; i < 4; i++)
        for (int j = 0; j < 4; j++)
            ob[(size_t)(row0 + ty * 4 + i) * DD + tx * 4 + j] = acc[i][j];
}

// ---------------- host launch ----------------
extern "C" void kernel_launch(void* const* d_in, const int* in_sizes, int n_in,
                              void* d_out, int out_size)
{
    const float* x     = (const float*)d_in[0];
    const int*   amask = (const int*)  d_in[1];
    const float* wq    = (const float*)d_in[2];
    const float* wk    = (const float*)d_in[3];
    const float* wv    = (const float*)d_in[4];
    const float* wo    = (const float*)d_in[5];
    const float* bo    = (const float*)d_in[6];
    const float* ln1s  = (const float*)d_in[7];
    const float* ln1b  = (const float*)d_in[8];
    const float* ln2s  = (const float*)d_in[9];
    const float* ln2b  = (const float*)d_in[10];
    const float* w1    = (const float*)d_in[11];
    const float* b1    = (const float*)d_in[12];
    const float* w2    = (const float*)d_in[13];
    const float* b2    = (const float*)d_in[14];
    float* out = (float*)d_out;

    float *h, *q, *k, *v, *ctx, *x2, *h2, *mid;
    cudaGetSymbolAddress((void**)&h,   g_h);
    cudaGetSymbolAddress((void**)&q,   g_q);
    cudaGetSymbolAddress((void**)&k,   g_k);
    cudaGetSymbolAddress((void**)&v,   g_v);
    cudaGetSymbolAddress((void**)&ctx, g_ctx);
    cudaGetSymbolAddress((void**)&x2,  g_x2);
    cudaGetSymbolAddress((void**)&h2,  g_h2);
    cudaGetSymbolAddress((void**)&mid, g_mid);

    // LN1
    ln_kernel<<<BS, 256>>>(x, ln1s, ln1b, h);

    // Q, K, V projections (tf32 tensor cores)
    dim3 gQKV(DD / 128, BS / 128);
    gemm_tf32<<<gQKV, 256>>>(h, wq, q, BS, DD, DD, nullptr, nullptr, 0);
    gemm_tf32<<<gQKV, 256>>>(h, wk, k, BS, DD, DD, nullptr, nullptr, 0);
    gemm_tf32<<<gQKV, 256>>>(h, wv, v, BS, DD, DD, nullptr, nullptr, 0);

    // attention
    scores_kernel<<<dim3(SS / 64, SS / 64, NBH), 256>>>(q, k, amask);
    softmax_kernel<<<NBH * SS, 256>>>();
    ctx_kernel<<<dim3(1, SS / 64, NBH), 256>>>(v);

    // output projection + residual
    gemm_tf32<<<gQKV, 256>>>(ctx, wo, x2, BS, DD, DD, bo, x, 0);

    // LN2 + FFN
    ln_kernel<<<BS, 256>>>(x2, ln2s, ln2b, h2);
    gemm_tf32<<<dim3(DFF / 128, BS / 128), 256>>>(h2, w1, mid, BS, DFF, DD, b1, nullptr, 1);
    gemm_tf32<<<dim3(DD / 128, BS / 128), 256>>>(mid, w2, out, BS, DD, DFF, b2, x2, 0);
}

// round 3
// speedup vs baseline: 5.9847x; 1.1706x over previous
#include <cuda_runtime.h>
#include <math.h>
#include <stdint.h>

#define BB 4
#define SS 1024
#define DD 1024
#define HH 16
#define HD 64
#define BS (BB*SS)     /* 4096 */
#define DFF (4*DD)     /* 4096 */

// ---------------- scratch (static __device__, no allocations) ----------------
__device__ float g_h  [BS*DD];
__device__ float g_q  [BS*DD];
__device__ float g_k  [BS*DD];
__device__ float g_v  [BS*DD];
__device__ float g_ctx[BS*DD];
__device__ float g_x2 [BS*DD];
__device__ float g_h2 [BS*DD];
__device__ float g_mid[BS*DFF];

// ---------------- helpers ----------------
__device__ __forceinline__ void cpa16(void* d, const void* s) {
    asm volatile("cp.async.cg.shared.global [%0], [%1], 16;\n"
                 :: "r"((uint32_t)__cvta_generic_to_shared(d)), "l"(s));
}
__device__ __forceinline__ void cp_commit() { asm volatile("cp.async.commit_group;\n"); }
__device__ __forceinline__ void cp_wait0()  { asm volatile("cp.async.wait_group 0;\n"); }

__device__ __forceinline__ void mma_tf32(float* c, uint32_t a0, uint32_t a1,
                                         uint32_t a2, uint32_t a3,
                                         uint32_t b0, uint32_t b1) {
    asm volatile(
        "mma.sync.aligned.m16n8k8.row.col.f32.tf32.tf32.f32 "
        "{%0,%1,%2,%3}, {%4,%5,%6,%7}, {%8,%9}, {%0,%1,%2,%3};"
        : "+f"(c[0]), "+f"(c[1]), "+f"(c[2]), "+f"(c[3])
        : "r"(a0), "r"(a1), "r"(a2), "r"(a3), "r"(b0), "r"(b1));
}

__device__ __forceinline__ uint32_t fu(float x) { return __float_as_uint(x); }

__device__ __forceinline__ float gelu_f(float x) {
    float t = 0.7978845608028654f * (x + 0.044715f * x * x * x);
    return 0.5f * x * (1.0f + tanhf(t));
}

// ---------------- layernorm: one block per row ----------------
__global__ void ln_kernel(const float* __restrict__ x,
                          const float* __restrict__ scale,
                          const float* __restrict__ shift,
                          float* __restrict__ out)
{
    int row = blockIdx.x;
    const float* xr = x + (size_t)row * DD;
    float* orow = out + (size_t)row * DD;
    __shared__ float red[256];
    int t = threadIdx.x;

    float s = 0.f;
    for (int i = t; i < DD; i += 256) s += xr[i];
    red[t] = s; __syncthreads();
    for (int o = 128; o > 0; o >>= 1) { if (t < o) red[t] += red[t + o]; __syncthreads(); }
    float mean = red[0] * (1.0f / DD);
    __syncthreads();

    float v = 0.f;
    for (int i = t; i < DD; i += 256) { float d = xr[i] - mean; v += d * d; }
    red[t] = v; __syncthreads();
    for (int o = 128; o > 0; o >>= 1) { if (t < o) red[t] += red[t + o]; __syncthreads(); }
    float rstd = rsqrtf(red[0] * (1.0f / DD) + 1e-5f);

    for (int i = t; i < DD; i += 256)
        orow[i] = scale[i] * (xr[i] - mean) * rstd + shift[i];
}

// ---------------- tf32 GEMM v3: cp.async double-buffered, 128x128x16 ----------------
// C[M,N] = A[M,K] @ B[K,N] (+bias[N]) (gelu?) (+res[M,N]); M,N mult 128, K mult 16.
__global__ __launch_bounds__(256, 2)
void gemm_tf32(const float* __restrict__ A, const float* __restrict__ Bm,
               float* __restrict__ C, int M, int N, int K,
               const float* __restrict__ bias,
               const float* __restrict__ res,
               int gelu)
{
    __shared__ float As[2][128][20];   // [m][k] pad 20 -> conflict-free A-frag LDS
    __shared__ float Bs[2][16][136];   // [k][n] pad 136 -> conflict-free B-frag LDS

    const int tid  = threadIdx.x;
    const int lane = tid & 31;
    const int warp = tid >> 5;
    const int g    = lane >> 2;
    const int tig  = lane & 3;
    const int mw   = (warp >> 2) * 64;
    const int nw   = (warp & 3) * 32;
    const int bx = blockIdx.x, by = blockIdx.y;

    // A loader: 2 chunks/thread. chunk c: row c>>2, kchunk c&3 (4 floats)
    const int ra = tid >> 2;          // 0..63
    const int ka = (tid & 3) * 4;     // 0,4,8,12
    const float* Ap = A + (size_t)(by * 128 + ra) * K + ka;
    // B loader: 2 chunks/thread. row tid>>5 (0..7), nchunk (tid&31)*4
    const int rb = tid >> 5;
    const int nb = (tid & 31) * 4;
    const float* Bp = Bm + (size_t)rb * N + bx * 128 + nb;

    float acc[4][4][4];
    #pragma unroll
    for (int i = 0; i < 4; i++)
        #pragma unroll
        for (int j = 0; j < 4; j++)
            #pragma unroll
            for (int c = 0; c < 4; c++) acc[i][j][c] = 0.f;

    // prologue: stage 0
    cpa16(&As[0][ra][ka],      Ap);
    cpa16(&As[0][ra + 64][ka], Ap + (size_t)64 * K);
    cpa16(&Bs[0][rb][nb],      Bp);
    cpa16(&Bs[0][rb + 8][nb],  Bp + (size_t)8 * N);
    cp_commit();

    int st = 0;
    for (int k0 = 0; k0 < K; k0 += 16) {
        cp_wait0();
        __syncthreads();
        if (k0 + 16 < K) {
            int sn = st ^ 1;
            cpa16(&As[sn][ra][ka],      Ap + (k0 + 16));
            cpa16(&As[sn][ra + 64][ka], Ap + (size_t)64 * K + (k0 + 16));
            cpa16(&Bs[sn][rb][nb],      Bp + (size_t)(k0 + 16) * N);
            cpa16(&Bs[sn][rb + 8][nb],  Bp + (size_t)(k0 + 24) * N);
            cp_commit();
        }
        #pragma unroll
        for (int kb = 0; kb < 16; kb += 8) {
            uint32_t a[4][4], b[4][2];
            #pragma unroll
            for (int i = 0; i < 4; i++) {
                int m = mw + i * 16 + g;
                a[i][0] = fu(As[st][m][kb + tig]);
                a[i][1] = fu(As[st][m + 8][kb + tig]);
                a[i][2] = fu(As[st][m][kb + tig + 4]);
                a[i][3] = fu(As[st][m + 8][kb + tig + 4]);
            }
            #pragma unroll
            for (int j = 0; j < 4; j++) {
                int n = nw + j * 8 + g;
                b[j][0] = fu(Bs[st][kb + tig][n]);
                b[j][1] = fu(Bs[st][kb + tig + 4][n]);
            }
            #pragma unroll
            for (int i = 0; i < 4; i++)
                #pragma unroll
                for (int j = 0; j < 4; j++)
                    mma_tf32(acc[i][j], a[i][0], a[i][1], a[i][2], a[i][3],
                             b[j][0], b[j][1]);
        }
        st ^= 1;
    }

    #pragma unroll
    for (int i = 0; i < 4; i++) {
        int row = by * 128 + mw + i * 16 + g;
        #pragma unroll
        for (int j = 0; j < 4; j++) {
            int col = bx * 128 + nw + j * 8 + tig * 2;
            float v0 = acc[i][j][0], v1 = acc[i][j][1];
            float v2 = acc[i][j][2], v3 = acc[i][j][3];
            if (bias) {
                float b0 = bias[col], b1 = bias[col + 1];
                v0 += b0; v1 += b1; v2 += b0; v3 += b1;
            }
            if (gelu) { v0 = gelu_f(v0); v1 = gelu_f(v1); v2 = gelu_f(v2); v3 = gelu_f(v3); }
            size_t o0 = (size_t)row * N + col;
            size_t o1 = (size_t)(row + 8) * N + col;
            if (res) {
                v0 += res[o0]; v1 += res[o0 + 1];
                v2 += res[o1]; v3 += res[o1 + 1];
            }
            C[o0] = v0; C[o0 + 1] = v1;
            C[o1] = v2; C[o1 + 1] = v3;
        }
    }
}

// ---------------- fused flash attention (tf32 MMA, online softmax) ----------------
// Q tile 128 rows per CTA, KV tiles of 64, causal. 8 warps; warp w owns rows
// [w*16, w*16+16). grid = (8 qtiles heavy-first, B*H).
#define FLASH_SMEM ((128*68 + 2*64*68 + 2*64*68 + 8*16*68 + 2*64) * 4)

__global__ __launch_bounds__(256)
void flash_kernel(const float* __restrict__ q, const float* __restrict__ k,
                  const float* __restrict__ v, const int* __restrict__ amask,
                  float* __restrict__ ctx)
{
    extern __shared__ float fsm[];
    float* Qs = fsm;                     // [128][68]
    float* Ks = Qs + 128 * 68;           // [2][64][68]
    float* Vs = Ks + 2 * 64 * 68;        // [2][64][68]
    float* Ps = Vs + 2 * 64 * 68;        // [8][16][68]
    float* mk = Ps + 8 * 16 * 68;        // [2][64]

    const int tid = threadIdx.x, w = tid >> 5, lane = tid & 31;
    const int g = lane >> 2, tig = lane & 3;
    const int bh = blockIdx.y, b = bh >> 4, h = bh & 15;
    const int row0 = (gridDim.x - 1 - blockIdx.x) * 128;   // heavy tiles first
    const int ntiles = row0 / 64 + 2;

    const float* qb = q + (size_t)(b * SS + row0) * DD + h * 64;
    const float* kb = k + (size_t)(b * SS) * DD + h * 64;
    const float* vb = v + (size_t)(b * SS) * DD + h * 64;

    // Q tile: 128 rows x 64 floats
    #pragma unroll
    for (int i = 0; i < 8; i++) {
        int c = tid + i * 256; int r = c >> 4, dc = (c & 15) * 4;
        cpa16(&Qs[r * 68 + dc], qb + (size_t)r * DD + dc);
    }
    // KV tile 0 into stage 0
    #pragma unroll
    for (int i = 0; i < 4; i++) {
        int c = tid + i * 256; int r = c >> 4, dc = (c & 15) * 4;
        cpa16(&Ks[r * 68 + dc], kb + (size_t)r * DD + dc);
        cpa16(&Vs[r * 68 + dc], vb + (size_t)r * DD + dc);
    }
    if (tid < 64) mk[tid] = amask[b * SS + tid] ? 0.f : -1e30f;
    cp_commit();

    float m0 = -1e30f, m1 = -1e30f, l0 = 0.f, l1 = 0.f;
    float acc_o[8][4];
    #pragma unroll
    for (int nt = 0; nt < 8; nt++)
        #pragma unroll
        for (int c = 0; c < 4; c++) acc_o[nt][c] = 0.f;

    const int mrow = w * 16 + g;
    const int grow0 = row0 + mrow, grow1 = grow0 + 8;
    float* Pw = Ps + w * 16 * 68;

    for (int t = 0; t < ntiles; t++) {
        const int st = t & 1;
        cp_wait0();
        __syncthreads();
        if (t + 1 < ntiles) {
            int j0n = (t + 1) * 64, sn = st ^ 1;
            const float* kn = kb + (size_t)j0n * DD;
            const float* vn = vb + (size_t)j0n * DD;
            #pragma unroll
            for (int i = 0; i < 4; i++) {
                int c = tid + i * 256; int r = c >> 4, dc = (c & 15) * 4;
                cpa16(&Ks[(sn * 64 + r) * 68 + dc], kn + (size_t)r * DD + dc);
                cpa16(&Vs[(sn * 64 + r) * 68 + dc], vn + (size_t)r * DD + dc);
            }
            if (tid < 64) mk[sn * 64 + tid] = amask[b * SS + j0n + tid] ? 0.f : -1e30f;
            cp_commit();
        }
        const int j0 = t * 64;
        const float* Ksb = Ks + st * 64 * 68;
        const float* Vsb = Vs + st * 64 * 68;
        const float* mkb = mk + st * 64;

        // ---- S = Q K^T ----
        float accs[8][4];
        #pragma unroll
        for (int nt = 0; nt < 8; nt++)
            #pragma unroll
            for (int c = 0; c < 4; c++) accs[nt][c] = 0.f;
        #pragma unroll
        for (int ks = 0; ks < 8; ks++) {
            uint32_t a0 = fu(Qs[mrow * 68 + ks * 8 + tig]);
            uint32_t a1 = fu(Qs[(mrow + 8) * 68 + ks * 8 + tig]);
            uint32_t a2 = fu(Qs[mrow * 68 + ks * 8 + tig + 4]);
            uint32_t a3 = fu(Qs[(mrow + 8) * 68 + ks * 8 + tig + 4]);
            #pragma unroll
            for (int nt = 0; nt < 8; nt++) {
                uint32_t b0 = fu(Ksb[(g + nt * 8) * 68 + ks * 8 + tig]);
                uint32_t b1 = fu(Ksb[(g + nt * 8) * 68 + ks * 8 + tig + 4]);
                mma_tf32(accs[nt], a0, a1, a2, a3, b0, b1);
            }
        }

        // ---- mask + scale + rowmax ----
        float rm0 = -1e30f, rm1 = -1e30f;
        #pragma unroll
        for (int nt = 0; nt < 8; nt++) {
            int c0 = j0 + nt * 8 + tig * 2;
            float ma = mkb[nt * 8 + tig * 2], mb = mkb[nt * 8 + tig * 2 + 1];
            float s0 = accs[nt][0] * 0.125f + ma;
            float s1 = accs[nt][1] * 0.125f + mb;
            float s2 = accs[nt][2] * 0.125f + ma;
            float s3 = accs[nt][3] * 0.125f + mb;
            if (c0 > grow0)     s0 = -1e30f;
            if (c0 + 1 > grow0) s1 = -1e30f;
            if (c0 > grow1)     s2 = -1e30f;
            if (c0 + 1 > grow1) s3 = -1e30f;
            accs[nt][0] = s0; accs[nt][1] = s1; accs[nt][2] = s2; accs[nt][3] = s3;
            rm0 = fmaxf(rm0, fmaxf(s0, s1));
            rm1 = fmaxf(rm1, fmaxf(s2, s3));
        }
        rm0 = fmaxf(rm0, __shfl_xor_sync(0xffffffffu, rm0, 1));
        rm0 = fmaxf(rm0, __shfl_xor_sync(0xffffffffu, rm0, 2));
        rm1 = fmaxf(rm1, __shfl_xor_sync(0xffffffffu, rm1, 1));
        rm1 = fmaxf(rm1, __shfl_xor_sync(0xffffffffu, rm1, 2));

        float mn0 = fmaxf(m0, rm0), mn1 = fmaxf(m1, rm1);
        float corr0 = __expf(m0 - mn0), corr1 = __expf(m1 - mn1);
        m0 = mn0; m1 = mn1;

        // ---- P = exp(S - m), row sums, stage P to warp-private smem ----
        float sum0 = 0.f, sum1 = 0.f;
        #pragma unroll
        for (int nt = 0; nt < 8; nt++) {
            float p0 = __expf(accs[nt][0] - m0);
            float p1 = __expf(accs[nt][1] - m0);
            float p2 = __expf(accs[nt][2] - m1);
            float p3 = __expf(accs[nt][3] - m1);
            sum0 += p0 + p1; sum1 += p2 + p3;
            *(float2*)&Pw[g * 68 + nt * 8 + tig * 2] = make_float2(p0, p1);
            *(float2*)&Pw[(g + 8) * 68 + nt * 8 + tig * 2] = make_float2(p2, p3);
        }
        sum0 += __shfl_xor_sync(0xffffffffu, sum0, 1);
        sum0 += __shfl_xor_sync(0xffffffffu, sum0, 2);
        sum1 += __shfl_xor_sync(0xffffffffu, sum1, 1);
        sum1 += __shfl_xor_sync(0xffffffffu, sum1, 2);
        l0 = l0 * corr0 + sum0;
        l1 = l1 * corr1 + sum1;
        #pragma unroll
        for (int nt = 0; nt < 8; nt++) {
            acc_o[nt][0] *= corr0; acc_o[nt][1] *= corr0;
            acc_o[nt][2] *= corr1; acc_o[nt][3] *= corr1;
        }
        __syncwarp();

        // ---- O += P V ----
        #pragma unroll
        for (int ks = 0; ks < 8; ks++) {
            uint32_t a0 = fu(Pw[g * 68 + ks * 8 + tig]);
            uint32_t a1 = fu(Pw[(g + 8) * 68 + ks * 8 + tig]);
            uint32_t a2 = fu(Pw[g * 68 + ks * 8 + tig + 4]);
            uint32_t a3 = fu(Pw[(g + 8) * 68 + ks * 8 + tig + 4]);
            #pragma unroll
            for (int nt = 0; nt < 8; nt++) {
                uint32_t b0 = fu(Vsb[(ks * 8 + tig) * 68 + nt * 8 + g]);
                uint32_t b1 = fu(Vsb[(ks * 8 + tig + 4) * 68 + nt * 8 + g]);
                mma_tf32(acc_o[nt], a0, a1, a2, a3, b0, b1);
            }
        }
    }

    // ---- epilogue: O /= l ----
    float i0 = 1.f / l0, i1 = 1.f / l1;
    size_t base0 = (size_t)(b * SS + grow0) * DD + h * 64;
    size_t base1 = (size_t)(b * SS + grow1) * DD + h * 64;
    #pragma unroll
    for (int nt = 0; nt < 8; nt++) {
        int col = nt * 8 + tig * 2;
        *(float2*)&ctx[base0 + col] = make_float2(acc_o[nt][0] * i0, acc_o[nt][1] * i0);
        *(float2*)&ctx[base1 + col] = make_float2(acc_o[nt][2] * i1, acc_o[nt][3] * i1);
    }
}

// ---------------- host launch ----------------
extern "C" void kernel_launch(void* const* d_in, const int* in_sizes, int n_in,
                              void* d_out, int out_size)
{
    const float* x     = (const float*)d_in[0];
    const int*   amask = (const int*)  d_in[1];
    const float* wq    = (const float*)d_in[2];
    const float* wk    = (const float*)d_in[3];
    const float* wv    = (const float*)d_in[4];
    const float* wo    = (const float*)d_in[5];
    const float* bo    = (const float*)d_in[6];
    const float* ln1s  = (const float*)d_in[7];
    const float* ln1b  = (const float*)d_in[8];
    const float* ln2s  = (const float*)d_in[9];
    const float* ln2b  = (const float*)d_in[10];
    const float* w1    = (const float*)d_in[11];
    const float* b1    = (const float*)d_in[12];
    const float* w2    = (const float*)d_in[13];
    const float* b2    = (const float*)d_in[14];
    float* out = (float*)d_out;

    float *h, *q, *k, *v, *ctx, *x2, *h2, *mid;
    cudaGetSymbolAddress((void**)&h,   g_h);
    cudaGetSymbolAddress((void**)&q,   g_q);
    cudaGetSymbolAddress((void**)&k,   g_k);
    cudaGetSymbolAddress((void**)&v,   g_v);
    cudaGetSymbolAddress((void**)&ctx, g_ctx);
    cudaGetSymbolAddress((void**)&x2,  g_x2);
    cudaGetSymbolAddress((void**)&h2,  g_h2);
    cudaGetSymbolAddress((void**)&mid, g_mid);

    static int smem_set = 0;
    if (!smem_set) {
        cudaFuncSetAttribute(flash_kernel,
                             cudaFuncAttributeMaxDynamicSharedMemorySize, FLASH_SMEM);
        smem_set = 1;
    }

    // LN1
    ln_kernel<<<BS, 256>>>(x, ln1s, ln1b, h);

    // Q, K, V projections
    dim3 gQKV(DD / 128, BS / 128);
    gemm_tf32<<<gQKV, 256>>>(h, wq, q, BS, DD, DD, nullptr, nullptr, 0);
    gemm_tf32<<<gQKV, 256>>>(h, wk, k, BS, DD, DD, nullptr, nullptr, 0);
    gemm_tf32<<<gQKV, 256>>>(h, wv, v, BS, DD, DD, nullptr, nullptr, 0);

    // fused attention
    flash_kernel<<<dim3(SS / 128, BB * HH), 256, FLASH_SMEM>>>(q, k, v, amask, ctx);

    // output projection + residual
    gemm_tf32<<<gQKV, 256>>>(ctx, wo, x2, BS, DD, DD, bo, x, 0);

    // LN2 + FFN
    ln_kernel<<<BS, 256>>>(x2, ln2s, ln2b, h2);
    gemm_tf32<<<dim3(DFF / 128, BS / 128), 256>>>(h2, w1, mid, BS, DFF, DD, b1, nullptr, 1);
    gemm_tf32<<<dim3(DD / 128, BS / 128), 256>>>(mid, w2, out, BS, DD, DFF, b2, x2, 0);
}

// round 5
// speedup vs baseline: 9.0478x; 1.5118x over previous
#include <cuda_runtime.h>
#include <math.h>
#include <stdint.h>

#define BB 4
#define SS 1024
#define DD 1024
#define HH 16
#define HD 64
#define BS (BB*SS)     /* 4096 */
#define DFF (4*DD)     /* 4096 */
#define QKVS 3072

// ---------------- scratch (static __device__, no allocations) ----------------
__device__ float g_h  [BS*DD];
__device__ float g_qkv[BS*QKVS];
__device__ float g_ctx[BS*DD];
__device__ float g_x2 [BS*DD];
__device__ float g_h2 [BS*DD];
__device__ float g_mid[BS*DFF];
__device__ float g_wt [21*1024*1024];  // wqkv(12M) woR(1M) w1R(4M) w2R(4M)

// ---------------- helpers ----------------
__device__ __forceinline__ void cpa16(void* d, const void* s) {
    asm volatile("cp.async.cg.shared.global [%0], [%1], 16;\n"
                 :: "r"((uint32_t)__cvta_generic_to_shared(d)), "l"(s));
}
__device__ __forceinline__ void cp_commit() { asm volatile("cp.async.commit_group;\n"); }
__device__ __forceinline__ void cp_wait0()  { asm volatile("cp.async.wait_group 0;\n"); }
__device__ __forceinline__ void cp_wait1()  { asm volatile("cp.async.wait_group 1;\n"); }

__device__ __forceinline__ uint32_t fu(float x) { return __float_as_uint(x); }

__device__ __forceinline__ float rna_f(float x) {
    uint32_t u;
    asm("cvt.rna.tf32.f32 %0, %1;" : "=r"(u) : "f"(x));
    return __uint_as_float(u);
}

__device__ __forceinline__ float gelu_f(float x) {
    float t = 0.7978845608028654f * (x + 0.044715f * x * x * x);
    return 0.5f * x * (1.0f + tanhf(t));
}

__device__ __forceinline__ void mma_tf32(float* c, uint32_t a0, uint32_t a1,
                                         uint32_t a2, uint32_t a3,
                                         uint32_t b0, uint32_t b1) {
    asm volatile(
        "mma.sync.aligned.m16n8k8.row.col.f32.tf32.tf32.f32 "
        "{%0,%1,%2,%3}, {%4,%5,%6,%7}, {%8,%9}, {%0,%1,%2,%3};"
        : "+f"(c[0]), "+f"(c[1]), "+f"(c[2]), "+f"(c[3])
        : "r"(a0), "r"(a1), "r"(a2), "r"(a3), "r"(b0), "r"(b1));
}

// ---------------- weight prep ----------------
__global__ void pack_qkv(const float* __restrict__ wq, const float* __restrict__ wk,
                         const float* __restrict__ wv, float* __restrict__ out)
{
    int idx = blockIdx.x * 256 + threadIdx.x;     // over 1024*1024
    int k = idx >> 10, n = idx & 1023;
    size_t o = (size_t)k * QKVS + n;
    out[o]        = rna_f(wq[idx]);
    out[o + 1024] = rna_f(wk[idx]);
    out[o + 2048] = rna_f(wv[idx]);
}

__global__ void round_copy(const float* __restrict__ in, float* __restrict__ out)
{
    int idx = blockIdx.x * 256 + threadIdx.x;
    float4 v = ((const float4*)in)[idx];
    ((float4*)out)[idx] = make_float4(rna_f(v.x), rna_f(v.y), rna_f(v.z), rna_f(v.w));
}

// ---------------- layernorm: one block per row, single pass, rna output ----------------
__global__ void ln_kernel(const float* __restrict__ x,
                          const float* __restrict__ scale,
                          const float* __restrict__ shift,
                          float* __restrict__ out)
{
    int row = blockIdx.x;
    int t = threadIdx.x;
    const float4 xv = ((const float4*)(x + (size_t)row * DD))[t];
    __shared__ float red[256];

    float s = xv.x + xv.y + xv.z + xv.w;
    red[t] = s; __syncthreads();
    for (int o = 128; o > 0; o >>= 1) { if (t < o) red[t] += red[t + o]; __syncthreads(); }
    float mean = red[0] * (1.0f / DD);
    __syncthreads();

    float d0 = xv.x - mean, d1 = xv.y - mean, d2 = xv.z - mean, d3 = xv.w - mean;
    red[t] = d0 * d0 + d1 * d1 + d2 * d2 + d3 * d3; __syncthreads();
    for (int o = 128; o > 0; o >>= 1) { if (t < o) red[t] += red[t + o]; __syncthreads(); }
    float rstd = rsqrtf(red[0] * (1.0f / DD) + 1e-5f);

    float4 sc = ((const float4*)scale)[t];
    float4 sh = ((const float4*)shift)[t];
    ((float4*)(out + (size_t)row * DD))[t] = make_float4(
        rna_f(sc.x * d0 * rstd + sh.x), rna_f(sc.y * d1 * rstd + sh.y),
        rna_f(sc.z * d2 * rstd + sh.z), rna_f(sc.w * d3 * rstd + sh.w));
}

// ---------------- tf32 GEMM v4: 3-stage cp.async pipeline, 128x128x16 ----------------
// C[M,N] = A[M,K] @ B[K,N] (+bias) (gelu?) (+res) (rna?); M,N mult 128, K mult 16.
#define ASZ (128*20)
#define BSZ (16*136)
#define STG (ASZ+BSZ)
#define GSMEM (3*STG*4)

__global__ __launch_bounds__(256, 2)
void gemm_tf32(const float* __restrict__ A, const float* __restrict__ Bm,
               float* __restrict__ C, int M, int N, int K,
               const float* __restrict__ bias,
               const float* __restrict__ res,
               int gelu, int rnd)
{
    extern __shared__ float sm[];
    const int tid  = threadIdx.x;
    const int lane = tid & 31;
    const int warp = tid >> 5;
    const int g    = lane >> 2;
    const int tig  = lane & 3;
    const int mw   = (warp >> 2) * 64;
    const int nw   = (warp & 3) * 32;
    const int bx = blockIdx.x, by = blockIdx.y;

    const int ra = tid >> 2, ka = (tid & 3) * 4;
    const int rb = tid >> 5, nb = (tid & 31) * 4;
    const float* Ap = A + (size_t)(by * 128 + ra) * K + ka;
    const float* Bp = Bm + (size_t)rb * N + bx * 128 + nb;

    float acc[4][4][4];
    #pragma unroll
    for (int i = 0; i < 4; i++)
        #pragma unroll
        for (int j = 0; j < 4; j++)
            #pragma unroll
            for (int c = 0; c < 4; c++) acc[i][j][c] = 0.f;

    const int T = K / 16;

    // stage issue helper (inlined twice below via macro)
#define ISSUE(sidx, k0) do {                                                   \
        float* As_ = sm + (sidx) * STG;                                        \
        float* Bs_ = sm + (sidx) * STG + ASZ;                                  \
        cpa16(&As_[ra * 20 + ka],        Ap + (k0));                           \
        cpa16(&As_[(ra + 64) * 20 + ka], Ap + (size_t)64 * K + (k0));          \
        cpa16(&Bs_[rb * 136 + nb],       Bp + (size_t)(k0) * N);               \
        cpa16(&Bs_[(rb + 8) * 136 + nb], Bp + (size_t)((k0) + 8) * N);         \
        cp_commit();                                                           \
    } while (0)

    ISSUE(0, 0);
    ISSUE(1, 16);

    int st = 0;
    for (int t = 0; t < T; t++) {
        if (t + 2 < T) cp_wait1(); else cp_wait0();
        __syncthreads();
        if (t + 2 < T) {
            int sn = st + 2; if (sn >= 3) sn -= 3;
            ISSUE(sn, (t + 2) * 16);
        }
        const float* As = sm + st * STG;
        const float* Bs = sm + st * STG + ASZ;
        #pragma unroll
        for (int kb = 0; kb < 16; kb += 8) {
            uint32_t a[4][4], b[4][2];
            #pragma unroll
            for (int i = 0; i < 4; i++) {
                int m = mw + i * 16 + g;
                a[i][0] = fu(As[m * 20 + kb + tig]);
                a[i][1] = fu(As[(m + 8) * 20 + kb + tig]);
                a[i][2] = fu(As[m * 20 + kb + tig + 4]);
                a[i][3] = fu(As[(m + 8) * 20 + kb + tig + 4]);
            }
            #pragma unroll
            for (int j = 0; j < 4; j++) {
                int n = nw + j * 8 + g;
                b[j][0] = fu(Bs[(kb + tig) * 136 + n]);
                b[j][1] = fu(Bs[(kb + tig + 4) * 136 + n]);
            }
            #pragma unroll
            for (int i = 0; i < 4; i++)
                #pragma unroll
                for (int j = 0; j < 4; j++)
                    mma_tf32(acc[i][j], a[i][0], a[i][1], a[i][2], a[i][3],
                             b[j][0], b[j][1]);
        }
        st++; if (st >= 3) st -= 3;
    }
#undef ISSUE

    #pragma unroll
    for (int i = 0; i < 4; i++) {
        int row = by * 128 + mw + i * 16 + g;
        #pragma unroll
        for (int j = 0; j < 4; j++) {
            int col = bx * 128 + nw + j * 8 + tig * 2;
            float v0 = acc[i][j][0], v1 = acc[i][j][1];
            float v2 = acc[i][j][2], v3 = acc[i][j][3];
            if (bias) {
                float b0 = bias[col], b1 = bias[col + 1];
                v0 += b0; v1 += b1; v2 += b0; v3 += b1;
            }
            if (gelu) { v0 = gelu_f(v0); v1 = gelu_f(v1); v2 = gelu_f(v2); v3 = gelu_f(v3); }
            size_t o0 = (size_t)row * N + col;
            size_t o1 = (size_t)(row + 8) * N + col;
            if (res) {
                v0 += res[o0]; v1 += res[o0 + 1];
                v2 += res[o1]; v3 += res[o1 + 1];
            }
            if (rnd) {
                v0 = rna_f(v0); v1 = rna_f(v1); v2 = rna_f(v2); v3 = rna_f(v3);
            }
            C[o0] = v0; C[o0 + 1] = v1;
            C[o1] = v2; C[o1 + 1] = v3;
        }
    }
}

// ---------------- fused flash attention (tf32 MMA, online softmax) ----------------
// Reads Q,K,V from packed qkv [BS][3072]: q at col 0, k at 1024, v at 2048.
#define FLASH_SMEM ((128*68 + 2*64*68 + 2*64*68 + 8*16*68 + 2*64) * 4)

__global__ __launch_bounds__(256)
void flash_kernel(const float* __restrict__ qkv, const int* __restrict__ amask,
                  float* __restrict__ ctx)
{
    extern __shared__ float fsm[];
    float* Qs = fsm;                     // [128][68]
    float* Ks = Qs + 128 * 68;           // [2][64][68]
    float* Vs = Ks + 2 * 64 * 68;        // [2][64][68]
    float* Ps = Vs + 2 * 64 * 68;        // [8][16][68]
    float* mk = Ps + 8 * 16 * 68;        // [2][64]

    const int tid = threadIdx.x, w = tid >> 5, lane = tid & 31;
    const int g = lane >> 2, tig = lane & 3;
    const int bh = blockIdx.y, b = bh >> 4, h = bh & 15;
    const int row0 = (gridDim.x - 1 - blockIdx.x) * 128;   // heavy tiles first
    const int ntiles = row0 / 64 + 2;

    const float* qb = qkv + (size_t)(b * SS + row0) * QKVS + h * 64;
    const float* kb = qkv + (size_t)(b * SS) * QKVS + 1024 + h * 64;
    const float* vb = qkv + (size_t)(b * SS) * QKVS + 2048 + h * 64;

    #pragma unroll
    for (int i = 0; i < 8; i++) {
        int c = tid + i * 256; int r = c >> 4, dc = (c & 15) * 4;
        cpa16(&Qs[r * 68 + dc], qb + (size_t)r * QKVS + dc);
    }
    #pragma unroll
    for (int i = 0; i < 4; i++) {
        int c = tid + i * 256; int r = c >> 4, dc = (c & 15) * 4;
        cpa16(&Ks[r * 68 + dc], kb + (size_t)r * QKVS + dc);
        cpa16(&Vs[r * 68 + dc], vb + (size_t)r * QKVS + dc);
    }
    if (tid < 64) mk[tid] = amask[b * SS + tid] ? 0.f : -1e30f;
    cp_commit();

    float m0 = -1e30f, m1 = -1e30f, l0 = 0.f, l1 = 0.f;
    float acc_o[8][4];
    #pragma unroll
    for (int nt = 0; nt < 8; nt++)
        #pragma unroll
        for (int c = 0; c < 4; c++) acc_o[nt][c] = 0.f;

    const int mrow = w * 16 + g;
    const int grow0 = row0 + mrow, grow1 = grow0 + 8;
    float* Pw = Ps + w * 16 * 68;

    for (int t = 0; t < ntiles; t++) {
        const int st = t & 1;
        cp_wait0();
        __syncthreads();
        if (t + 1 < ntiles) {
            int j0n = (t + 1) * 64, sn = st ^ 1;
            const float* kn = kb + (size_t)j0n * QKVS;
            const float* vn = vb + (size_t)j0n * QKVS;
            #pragma unroll
            for (int i = 0; i < 4; i++) {
                int c = tid + i * 256; int r = c >> 4, dc = (c & 15) * 4;
                cpa16(&Ks[(sn * 64 + r) * 68 + dc], kn + (size_t)r * QKVS + dc);
                cpa16(&Vs[(sn * 64 + r) * 68 + dc], vn + (size_t)r * QKVS + dc);
            }
            if (tid < 64) mk[sn * 64 + tid] = amask[b * SS + j0n + tid] ? 0.f : -1e30f;
            cp_commit();
        }
        const int j0 = t * 64;
        const float* Ksb = Ks + st * 64 * 68;
        const float* Vsb = Vs + st * 64 * 68;
        const float* mkb = mk + st * 64;

        float accs[8][4];
        #pragma unroll
        for (int nt = 0; nt < 8; nt++)
            #pragma unroll
            for (int c = 0; c < 4; c++) accs[nt][c] = 0.f;
        #pragma unroll
        for (int ks = 0; ks < 8; ks++) {
            uint32_t a0 = fu(Qs[mrow * 68 + ks * 8 + tig]);
            uint32_t a1 = fu(Qs[(mrow + 8) * 68 + ks * 8 + tig]);
            uint32_t a2 = fu(Qs[mrow * 68 + ks * 8 + tig + 4]);
            uint32_t a3 = fu(Qs[(mrow + 8) * 68 + ks * 8 + tig + 4]);
            #pragma unroll
            for (int nt = 0; nt < 8; nt++) {
                uint32_t b0 = fu(Ksb[(g + nt * 8) * 68 + ks * 8 + tig]);
                uint32_t b1 = fu(Ksb[(g + nt * 8) * 68 + ks * 8 + tig + 4]);
                mma_tf32(accs[nt], a0, a1, a2, a3, b0, b1);
            }
        }

        float rm0 = -1e30f, rm1 = -1e30f;
        #pragma unroll
        for (int nt = 0; nt < 8; nt++) {
            int c0 = j0 + nt * 8 + tig * 2;
            float ma = mkb[nt * 8 + tig * 2], mb = mkb[nt * 8 + tig * 2 + 1];
            float s0 = accs[nt][0] * 0.125f + ma;
            float s1 = accs[nt][1] * 0.125f + mb;
            float s2 = accs[nt][2] * 0.125f + ma;
            float s3 = accs[nt][3] * 0.125f + mb;
            if (c0 > grow0)     s0 = -1e30f;
            if (c0 + 1 > grow0) s1 = -1e30f;
            if (c0 > grow1)     s2 = -1e30f;
            if (c0 + 1 > grow1) s3 = -1e30f;
            accs[nt][0] = s0; accs[nt][1] = s1; accs[nt][2] = s2; accs[nt][3] = s3;
            rm0 = fmaxf(rm0, fmaxf(s0, s1));
            rm1 = fmaxf(rm1, fmaxf(s2, s3));
        }
        rm0 = fmaxf(rm0, __shfl_xor_sync(0xffffffffu, rm0, 1));
        rm0 = fmaxf(rm0, __shfl_xor_sync(0xffffffffu, rm0, 2));
        rm1 = fmaxf(rm1, __shfl_xor_sync(0xffffffffu, rm1, 1));
        rm1 = fmaxf(rm1, __shfl_xor_sync(0xffffffffu, rm1, 2));

        float mn0 = fmaxf(m0, rm0), mn1 = fmaxf(m1, rm1);
        float corr0 = __expf(m0 - mn0), corr1 = __expf(m1 - mn1);
        m0 = mn0; m1 = mn1;

        float sum0 = 0.f, sum1 = 0.f;
        #pragma unroll
        for (int nt = 0; nt < 8; nt++) {
            float p0 = __expf(accs[nt][0] - m0);
            float p1 = __expf(accs[nt][1] - m0);
            float p2 = __expf(accs[nt][2] - m1);
            float p3 = __expf(accs[nt][3] - m1);
            sum0 += p0 + p1; sum1 += p2 + p3;
            *(float2*)&Pw[g * 68 + nt * 8 + tig * 2] = make_float2(p0, p1);
            *(float2*)&Pw[(g + 8) * 68 + nt * 8 + tig * 2] = make_float2(p2, p3);
        }
        sum0 += __shfl_xor_sync(0xffffffffu, sum0, 1);
        sum0 += __shfl_xor_sync(0xffffffffu, sum0, 2);
        sum1 += __shfl_xor_sync(0xffffffffu, sum1, 1);
        sum1 += __shfl_xor_sync(0xffffffffu, sum1, 2);
        l0 = l0 * corr0 + sum0;
        l1 = l1 * corr1 + sum1;
        #pragma unroll
        for (int nt = 0; nt < 8; nt++) {
            acc_o[nt][0] *= corr0; acc_o[nt][1] *= corr0;
            acc_o[nt][2] *= corr1; acc_o[nt][3] *= corr1;
        }
        __syncwarp();

        #pragma unroll
        for (int ks = 0; ks < 8; ks++) {
            uint32_t a0 = fu(Pw[g * 68 + ks * 8 + tig]);
            uint32_t a1 = fu(Pw[(g + 8) * 68 + ks * 8 + tig]);
            uint32_t a2 = fu(Pw[g * 68 + ks * 8 + tig + 4]);
            uint32_t a3 = fu(Pw[(g + 8) * 68 + ks * 8 + tig + 4]);
            #pragma unroll
            for (int nt = 0; nt < 8; nt++) {
                uint32_t b0 = fu(Vsb[(ks * 8 + tig) * 68 + nt * 8 + g]);
                uint32_t b1 = fu(Vsb[(ks * 8 + tig + 4) * 68 + nt * 8 + g]);
                mma_tf32(acc_o[nt], a0, a1, a2, a3, b0, b1);
            }
        }
    }

    float i0 = 1.f / l0, i1 = 1.f / l1;
    size_t base0 = (size_t)(b * SS + grow0) * DD + h * 64;
    size_t base1 = (size_t)(b * SS + grow1) * DD + h * 64;
    #pragma unroll
    for (int nt = 0; nt < 8; nt++) {
        int col = nt * 8 + tig * 2;
        *(float2*)&ctx[base0 + col] = make_float2(rna_f(acc_o[nt][0] * i0),
                                                  rna_f(acc_o[nt][1] * i0));
        *(float2*)&ctx[base1 + col] = make_float2(rna_f(acc_o[nt][2] * i1),
                                                  rna_f(acc_o[nt][3] * i1));
    }
}

// ---------------- host launch ----------------
extern "C" void kernel_launch(void* const* d_in, const int* in_sizes, int n_in,
                              void* d_out, int out_size)
{
    const float* x     = (const float*)d_in[0];
    const int*   amask = (const int*)  d_in[1];
    const float* wq    = (const float*)d_in[2];
    const float* wk    = (const float*)d_in[3];
    const float* wv    = (const float*)d_in[4];
    const float* wo    = (const float*)d_in[5];
    const float* bo    = (const float*)d_in[6];
    const float* ln1s  = (const float*)d_in[7];
    const float* ln1b  = (const float*)d_in[8];
    const float* ln2s  = (const float*)d_in[9];
    const float* ln2b  = (const float*)d_in[10];
    const float* w1    = (const float*)d_in[11];
    const float* b1    = (const float*)d_in[12];
    const float* w2    = (const float*)d_in[13];
    const float* b2    = (const float*)d_in[14];
    float* out = (float*)d_out;

    float *h, *qkv, *ctx, *x2, *h2, *mid, *wt;
    cudaGetSymbolAddress((void**)&h,   g_h);
    cudaGetSymbolAddress((void**)&qkv, g_qkv);
    cudaGetSymbolAddress((void**)&ctx, g_ctx);
    cudaGetSymbolAddress((void**)&x2,  g_x2);
    cudaGetSymbolAddress((void**)&h2,  g_h2);
    cudaGetSymbolAddress((void**)&mid, g_mid);
    cudaGetSymbolAddress((void**)&wt,  g_wt);

    float* wqkv = wt;                          // [1024][3072]
    float* woR  = wt + 12 * 1024 * 1024;       // [1024][1024]
    float* w1R  = wt + 13 * 1024 * 1024;       // [1024][4096]
    float* w2R  = wt + 17 * 1024 * 1024;       // [4096][1024]

    cudaFuncSetAttribute(flash_kernel,
                         cudaFuncAttributeMaxDynamicSharedMemorySize, FLASH_SMEM);
    cudaFuncSetAttribute(gemm_tf32,
                         cudaFuncAttributeMaxDynamicSharedMemorySize, GSMEM);

    // weight prep (rna-rounded tf32)
    pack_qkv<<<4096, 256>>>(wq, wk, wv, wqkv);
    round_copy<<<1024, 256>>>(wo, woR);
    round_copy<<<4096, 256>>>(w1, w1R);
    round_copy<<<4096, 256>>>(w2, w2R);

    // LN1 (rounded output)
    ln_kernel<<<BS, 256>>>(x, ln1s, ln1b, h);

    // fused QKV projection
    gemm_tf32<<<dim3(QKVS / 128, BS / 128), 256, GSMEM>>>(
        h, wqkv, qkv, BS, QKVS, DD, nullptr, nullptr, 0, 1);

    // fused attention
    flash_kernel<<<dim3(SS / 128, BB * HH), 256, FLASH_SMEM>>>(qkv, amask, ctx);

    // output projection + residual (exact fp32 output)
    gemm_tf32<<<dim3(DD / 128, BS / 128), 256, GSMEM>>>(
        ctx, woR, x2, BS, DD, DD, bo, x, 0, 0);

    // LN2 + FFN
    ln_kernel<<<BS, 256>>>(x2, ln2s, ln2b, h2);
    gemm_tf32<<<dim3(DFF / 128, BS / 128), 256, GSMEM>>>(
        h2, w1R, mid, BS, DFF, DD, b1, nullptr, 1, 1);
    gemm_tf32<<<dim3(DD / 128, BS / 128), 256, GSMEM>>>(
        mid, w2R, out, BS, DD, DFF, b2, x2, 0, 0);
}

// round 6
// speedup vs baseline: 9.1120x; 1.0071x over previous
#include <cuda_runtime.h>
#include <math.h>
#include <stdint.h>

#define BB 4
#define SS 1024
#define DD 1024
#define HH 16
#define HD 64
#define BS (BB*SS)     /* 4096 */
#define DFF (4*DD)     /* 4096 */
#define QKVS 3072

// ---------------- scratch (static __device__, no allocations) ----------------
__device__ float g_h  [BS*DD];
__device__ float g_qkv[BS*QKVS];
__device__ float g_ctx[BS*DD];
__device__ float g_x2 [BS*DD];
__device__ float g_h2 [BS*DD];
__device__ float g_mid[BS*DFF];
__device__ float g_wt [12*1024*1024];  // packed qkv weights [1024][3072]

// ---------------- helpers ----------------
__device__ __forceinline__ void cpa16(void* d, const void* s) {
    asm volatile("cp.async.cg.shared.global [%0], [%1], 16;\n"
                 :: "r"((uint32_t)__cvta_generic_to_shared(d)), "l"(s));
}
__device__ __forceinline__ void cp_commit() { asm volatile("cp.async.commit_group;\n"); }
__device__ __forceinline__ void cp_wait0()  { asm volatile("cp.async.wait_group 0;\n"); }
__device__ __forceinline__ void cp_wait1()  { asm volatile("cp.async.wait_group 1;\n"); }
__device__ __forceinline__ void cp_wait2()  { asm volatile("cp.async.wait_group 2;\n"); }

__device__ __forceinline__ uint32_t fu(float x) { return __float_as_uint(x); }

__device__ __forceinline__ float rna_f(float x) {
    uint32_t u;
    asm("cvt.rna.tf32.f32 %0, %1;" : "=r"(u) : "f"(x));
    return __uint_as_float(u);
}

__device__ __forceinline__ float gelu_f(float x) {
    float t = 0.7978845608028654f * (x + 0.044715f * x * x * x);
    return 0.5f * x * (1.0f + tanhf(t));
}

__device__ __forceinline__ void mma_tf32(float* c, uint32_t a0, uint32_t a1,
                                         uint32_t a2, uint32_t a3,
                                         uint32_t b0, uint32_t b1) {
    asm volatile(
        "mma.sync.aligned.m16n8k8.row.col.f32.tf32.tf32.f32 "
        "{%0,%1,%2,%3}, {%4,%5,%6,%7}, {%8,%9}, {%0,%1,%2,%3};"
        : "+f"(c[0]), "+f"(c[1]), "+f"(c[2]), "+f"(c[3])
        : "r"(a0), "r"(a1), "r"(a2), "r"(a3), "r"(b0), "r"(b1));
}

// ---------------- weight prep: pack Q,K,V weights (rna-rounded) ----------------
__global__ void pack_qkv(const float* __restrict__ wq, const float* __restrict__ wk,
                         const float* __restrict__ wv, float* __restrict__ out)
{
    int idx = blockIdx.x * 256 + threadIdx.x;     // over 1024*1024
    int k = idx >> 10, n = idx & 1023;
    size_t o = (size_t)k * QKVS + n;
    out[o]        = rna_f(wq[idx]);
    out[o + 1024] = rna_f(wk[idx]);
    out[o + 2048] = rna_f(wv[idx]);
}

// ---------------- layernorm: one block per row, single pass, rna output ----------------
__global__ void ln_kernel(const float* __restrict__ x,
                          const float* __restrict__ scale,
                          const float* __restrict__ shift,
                          float* __restrict__ out)
{
    int row = blockIdx.x;
    int t = threadIdx.x;
    const float4 xv = ((const float4*)(x + (size_t)row * DD))[t];
    __shared__ float red[256];

    float s = xv.x + xv.y + xv.z + xv.w;
    red[t] = s; __syncthreads();
    for (int o = 128; o > 0; o >>= 1) { if (t < o) red[t] += red[t + o]; __syncthreads(); }
    float mean = red[0] * (1.0f / DD);
    __syncthreads();

    float d0 = xv.x - mean, d1 = xv.y - mean, d2 = xv.z - mean, d3 = xv.w - mean;
    red[t] = d0 * d0 + d1 * d1 + d2 * d2 + d3 * d3; __syncthreads();
    for (int o = 128; o > 0; o >>= 1) { if (t < o) red[t] += red[t + o]; __syncthreads(); }
    float rstd = rsqrtf(red[0] * (1.0f / DD) + 1e-5f);

    float4 sc = ((const float4*)scale)[t];
    float4 sh = ((const float4*)shift)[t];
    ((float4*)(out + (size_t)row * DD))[t] = make_float4(
        rna_f(sc.x * d0 * rstd + sh.x), rna_f(sc.y * d1 * rstd + sh.y),
        rna_f(sc.z * d2 * rstd + sh.z), rna_f(sc.w * d3 * rstd + sh.w));
}

// ---------------- tf32 GEMM v5: 128x256 CTA tile, 64x64 warps, 4-stage cp.async ----
// C[M,N] = A[M,K] @ B[K,N] (+bias) (gelu?) (+res) (rna?); M mult 128, N mult 256,
// K mult 16.
#define ASZ (128*20)
#define BSZ (16*264)
#define STG (ASZ+BSZ)
#define GSMEM (4*STG*4)

__global__ __launch_bounds__(256, 1)
void gemm_tf32(const float* __restrict__ A, const float* __restrict__ Bm,
               float* __restrict__ C, int M, int N, int K,
               const float* __restrict__ bias,
               const float* __restrict__ res,
               int gelu, int rnd)
{
    extern __shared__ float sm[];
    const int tid  = threadIdx.x;
    const int lane = tid & 31;
    const int warp = tid >> 5;
    const int g    = lane >> 2;
    const int tig  = lane & 3;
    const int mw   = (warp >> 2) * 64;   // 0 or 64
    const int nw   = (warp & 3) * 64;    // 0,64,128,192
    const int bx = blockIdx.x, by = blockIdx.y;

    // A loader: 2 chunks/thread (rows ra, ra+64; k-chunk ka)
    const int ra = tid >> 2, ka = (tid & 3) * 4;
    const float* Ap = A + (size_t)(by * 128 + ra) * K + ka;
    // B loader: 4 chunks/thread; chunk c: row c>>6 (16 rows), col (c&63)*4
    const float* Bp = Bm + (size_t)(bx * 256);

    float acc[4][8][4];
    #pragma unroll
    for (int i = 0; i < 4; i++)
        #pragma unroll
        for (int j = 0; j < 8; j++)
            #pragma unroll
            for (int c = 0; c < 4; c++) acc[i][j][c] = 0.f;

    const int T = K / 16;

#define ISSUE(sidx, k0) do {                                                    \
        float* As_ = sm + (sidx) * STG;                                         \
        float* Bs_ = sm + (sidx) * STG + ASZ;                                   \
        cpa16(&As_[ra * 20 + ka],        Ap + (k0));                            \
        cpa16(&As_[(ra + 64) * 20 + ka], Ap + (size_t)64 * K + (k0));           \
        _Pragma("unroll")                                                       \
        for (int i_ = 0; i_ < 4; i_++) {                                        \
            int c_ = tid + i_ * 256;                                            \
            int r_ = c_ >> 6, n4_ = (c_ & 63) * 4;                              \
            cpa16(&Bs_[r_ * 264 + n4_], Bp + (size_t)((k0) + r_) * N + n4_);    \
        }                                                                       \
        cp_commit();                                                            \
    } while (0)

    ISSUE(0, 0);
    if (T > 1) ISSUE(1, 16);
    if (T > 2) ISSUE(2, 32);

    for (int t = 0; t < T; t++) {
        if (t < T - 2)      cp_wait2();
        else if (t == T - 2) cp_wait1();
        else                 cp_wait0();
        __syncthreads();
        if (t + 3 < T) ISSUE((t + 3) & 3, (t + 3) * 16);

        const float* As = sm + (t & 3) * STG;
        const float* Bs = sm + (t & 3) * STG + ASZ;
        #pragma unroll
        for (int kb = 0; kb < 16; kb += 8) {
            uint32_t a[4][4], b[8][2];
            #pragma unroll
            for (int i = 0; i < 4; i++) {
                int m = mw + i * 16 + g;
                a[i][0] = fu(As[m * 20 + kb + tig]);
                a[i][1] = fu(As[(m + 8) * 20 + kb + tig]);
                a[i][2] = fu(As[m * 20 + kb + tig + 4]);
                a[i][3] = fu(As[(m + 8) * 20 + kb + tig + 4]);
            }
            #pragma unroll
            for (int j = 0; j < 8; j++) {
                int n = nw + j * 8 + g;
                b[j][0] = fu(Bs[(kb + tig) * 264 + n]);
                b[j][1] = fu(Bs[(kb + tig + 4) * 264 + n]);
            }
            #pragma unroll
            for (int i = 0; i < 4; i++)
                #pragma unroll
                for (int j = 0; j < 8; j++)
                    mma_tf32(acc[i][j], a[i][0], a[i][1], a[i][2], a[i][3],
                             b[j][0], b[j][1]);
        }
    }
#undef ISSUE

    #pragma unroll
    for (int i = 0; i < 4; i++) {
        int row = by * 128 + mw + i * 16 + g;
        #pragma unroll
        for (int j = 0; j < 8; j++) {
            int col = bx * 256 + nw + j * 8 + tig * 2;
            float v0 = acc[i][j][0], v1 = acc[i][j][1];
            float v2 = acc[i][j][2], v3 = acc[i][j][3];
            if (bias) {
                float b0 = bias[col], b1 = bias[col + 1];
                v0 += b0; v1 += b1; v2 += b0; v3 += b1;
            }
            if (gelu) { v0 = gelu_f(v0); v1 = gelu_f(v1); v2 = gelu_f(v2); v3 = gelu_f(v3); }
            size_t o0 = (size_t)row * N + col;
            size_t o1 = (size_t)(row + 8) * N + col;
            if (res) {
                v0 += res[o0]; v1 += res[o0 + 1];
                v2 += res[o1]; v3 += res[o1 + 1];
            }
            if (rnd) {
                v0 = rna_f(v0); v1 = rna_f(v1); v2 = rna_f(v2); v3 = rna_f(v3);
            }
            C[o0] = v0; C[o0 + 1] = v1;
            C[o1] = v2; C[o1 + 1] = v3;
        }
    }
}

// ---------------- fused flash attention (tf32 MMA, online softmax) ----------------
// Reads Q,K,V from packed qkv [BS][3072]: q at col 0, k at 1024, v at 2048.
#define FLASH_SMEM ((128*68 + 2*64*68 + 2*64*68 + 8*16*68 + 2*64) * 4)

__global__ __launch_bounds__(256)
void flash_kernel(const float* __restrict__ qkv, const int* __restrict__ amask,
                  float* __restrict__ ctx)
{
    extern __shared__ float fsm[];
    float* Qs = fsm;                     // [128][68]
    float* Ks = Qs + 128 * 68;           // [2][64][68]
    float* Vs = Ks + 2 * 64 * 68;        // [2][64][68]
    float* Ps = Vs + 2 * 64 * 68;        // [8][16][68]
    float* mk = Ps + 8 * 16 * 68;        // [2][64]

    const int tid = threadIdx.x, w = tid >> 5, lane = tid & 31;
    const int g = lane >> 2, tig = lane & 3;
    const int bh = blockIdx.y, b = bh >> 4, h = bh & 15;
    const int row0 = (gridDim.x - 1 - blockIdx.x) * 128;   // heavy tiles first
    const int ntiles = row0 / 64 + 2;

    const float* qb = qkv + (size_t)(b * SS + row0) * QKVS + h * 64;
    const float* kb = qkv + (size_t)(b * SS) * QKVS + 1024 + h * 64;
    const float* vb = qkv + (size_t)(b * SS) * QKVS + 2048 + h * 64;

    #pragma unroll
    for (int i = 0; i < 8; i++) {
        int c = tid + i * 256; int r = c >> 4, dc = (c & 15) * 4;
        cpa16(&Qs[r * 68 + dc], qb + (size_t)r * QKVS + dc);
    }
    #pragma unroll
    for (int i = 0; i < 4; i++) {
        int c = tid + i * 256; int r = c >> 4, dc = (c & 15) * 4;
        cpa16(&Ks[r * 68 + dc], kb + (size_t)r * QKVS + dc);
        cpa16(&Vs[r * 68 + dc], vb + (size_t)r * QKVS + dc);
    }
    if (tid < 64) mk[tid] = amask[b * SS + tid] ? 0.f : -1e30f;
    cp_commit();

    float m0 = -1e30f, m1 = -1e30f, l0 = 0.f, l1 = 0.f;
    float acc_o[8][4];
    #pragma unroll
    for (int nt = 0; nt < 8; nt++)
        #pragma unroll
        for (int c = 0; c < 4; c++) acc_o[nt][c] = 0.f;

    const int mrow = w * 16 + g;
    const int grow0 = row0 + mrow, grow1 = grow0 + 8;
    float* Pw = Ps + w * 16 * 68;

    for (int t = 0; t < ntiles; t++) {
        const int st = t & 1;
        cp_wait0();
        __syncthreads();
        if (t + 1 < ntiles) {
            int j0n = (t + 1) * 64, sn = st ^ 1;
            const float* kn = kb + (size_t)j0n * QKVS;
            const float* vn = vb + (size_t)j0n * QKVS;
            #pragma unroll
            for (int i = 0; i < 4; i++) {
                int c = tid + i * 256; int r = c >> 4, dc = (c & 15) * 4;
                cpa16(&Ks[(sn * 64 + r) * 68 + dc], kn + (size_t)r * QKVS + dc);
                cpa16(&Vs[(sn * 64 + r) * 68 + dc], vn + (size_t)r * QKVS + dc);
            }
            if (tid < 64) mk[sn * 64 + tid] = amask[b * SS + j0n + tid] ? 0.f : -1e30f;
            cp_commit();
        }
        const int j0 = t * 64;
        const float* Ksb = Ks + st * 64 * 68;
        const float* Vsb = Vs + st * 64 * 68;
        const float* mkb = mk + st * 64;

        float accs[8][4];
        #pragma unroll
        for (int nt = 0; nt < 8; nt++)
            #pragma unroll
            for (int c = 0; c < 4; c++) accs[nt][c] = 0.f;
        #pragma unroll
        for (int ks = 0; ks < 8; ks++) {
            uint32_t a0 = fu(Qs[mrow * 68 + ks * 8 + tig]);
            uint32_t a1 = fu(Qs[(mrow + 8) * 68 + ks * 8 + tig]);
            uint32_t a2 = fu(Qs[mrow * 68 + ks * 8 + tig + 4]);
            uint32_t a3 = fu(Qs[(mrow + 8) * 68 + ks * 8 + tig + 4]);
            #pragma unroll
            for (int nt = 0; nt < 8; nt++) {
                uint32_t b0 = fu(Ksb[(g + nt * 8) * 68 + ks * 8 + tig]);
                uint32_t b1 = fu(Ksb[(g + nt * 8) * 68 + ks * 8 + tig + 4]);
                mma_tf32(accs[nt], a0, a1, a2, a3, b0, b1);
            }
        }

        float rm0 = -1e30f, rm1 = -1e30f;
        #pragma unroll
        for (int nt = 0; nt < 8; nt++) {
            int c0 = j0 + nt * 8 + tig * 2;
            float ma = mkb[nt * 8 + tig * 2], mb = mkb[nt * 8 + tig * 2 + 1];
            float s0 = accs[nt][0] * 0.125f + ma;
            float s1 = accs[nt][1] * 0.125f + mb;
            float s2 = accs[nt][2] * 0.125f + ma;
            float s3 = accs[nt][3] * 0.125f + mb;
            if (c0 > grow0)     s0 = -1e30f;
            if (c0 + 1 > grow0) s1 = -1e30f;
            if (c0 > grow1)     s2 = -1e30f;
            if (c0 + 1 > grow1) s3 = -1e30f;
            accs[nt][0] = s0; accs[nt][1] = s1; accs[nt][2] = s2; accs[nt][3] = s3;
            rm0 = fmaxf(rm0, fmaxf(s0, s1));
            rm1 = fmaxf(rm1, fmaxf(s2, s3));
        }
        rm0 = fmaxf(rm0, __shfl_xor_sync(0xffffffffu, rm0, 1));
        rm0 = fmaxf(rm0, __shfl_xor_sync(0xffffffffu, rm0, 2));
        rm1 = fmaxf(rm1, __shfl_xor_sync(0xffffffffu, rm1, 1));
        rm1 = fmaxf(rm1, __shfl_xor_sync(0xffffffffu, rm1, 2));

        float mn0 = fmaxf(m0, rm0), mn1 = fmaxf(m1, rm1);
        float corr0 = __expf(m0 - mn0), corr1 = __expf(m1 - mn1);
        m0 = mn0; m1 = mn1;

        float sum0 = 0.f, sum1 = 0.f;
        #pragma unroll
        for (int nt = 0; nt < 8; nt++) {
            float p0 = __expf(accs[nt][0] - m0);
            float p1 = __expf(accs[nt][1] - m0);
            float p2 = __expf(accs[nt][2] - m1);
            float p3 = __expf(accs[nt][3] - m1);
            sum0 += p0 + p1; sum1 += p2 + p3;
            *(float2*)&Pw[g * 68 + nt * 8 + tig * 2] = make_float2(p0, p1);
            *(float2*)&Pw[(g + 8) * 68 + nt * 8 + tig * 2] = make_float2(p2, p3);
        }
        sum0 += __shfl_xor_sync(0xffffffffu, sum0, 1);
        sum0 += __shfl_xor_sync(0xffffffffu, sum0, 2);
        sum1 += __shfl_xor_sync(0xffffffffu, sum1, 1);
        sum1 += __shfl_xor_sync(0xffffffffu, sum1, 2);
        l0 = l0 * corr0 + sum0;
        l1 = l1 * corr1 + sum1;
        #pragma unroll
        for (int nt = 0; nt < 8; nt++) {
            acc_o[nt][0] *= corr0; acc_o[nt][1] *= corr0;
            acc_o[nt][2] *= corr1; acc_o[nt][3] *= corr1;
        }
        __syncwarp();

        #pragma unroll
        for (int ks = 0; ks < 8; ks++) {
            uint32_t a0 = fu(Pw[g * 68 + ks * 8 + tig]);
            uint32_t a1 = fu(Pw[(g + 8) * 68 + ks * 8 + tig]);
            uint32_t a2 = fu(Pw[g * 68 + ks * 8 + tig + 4]);
            uint32_t a3 = fu(Pw[(g + 8) * 68 + ks * 8 + tig + 4]);
            #pragma unroll
            for (int nt = 0; nt < 8; nt++) {
                uint32_t b0 = fu(Vsb[(ks * 8 + tig) * 68 + nt * 8 + g]);
                uint32_t b1 = fu(Vsb[(ks * 8 + tig + 4) * 68 + nt * 8 + g]);
                mma_tf32(acc_o[nt], a0, a1, a2, a3, b0, b1);
            }
        }
    }

    float i0 = 1.f / l0, i1 = 1.f / l1;
    size_t base0 = (size_t)(b * SS + grow0) * DD + h * 64;
    size_t base1 = (size_t)(b * SS + grow1) * DD + h * 64;
    #pragma unroll
    for (int nt = 0; nt < 8; nt++) {
        int col = nt * 8 + tig * 2;
        *(float2*)&ctx[base0 + col] = make_float2(rna_f(acc_o[nt][0] * i0),
                                                  rna_f(acc_o[nt][1] * i0));
        *(float2*)&ctx[base1 + col] = make_float2(rna_f(acc_o[nt][2] * i1),
                                                  rna_f(acc_o[nt][3] * i1));
    }
}

// ---------------- host launch ----------------
extern "C" void kernel_launch(void* const* d_in, const int* in_sizes, int n_in,
                              void* d_out, int out_size)
{
    const float* x     = (const float*)d_in[0];
    const int*   amask = (const int*)  d_in[1];
    const float* wq    = (const float*)d_in[2];
    const float* wk    = (const float*)d_in[3];
    const float* wv    = (const float*)d_in[4];
    const float* wo    = (const float*)d_in[5];
    const float* bo    = (const float*)d_in[6];
    const float* ln1s  = (const float*)d_in[7];
    const float* ln1b  = (const float*)d_in[8];
    const float* ln2s  = (const float*)d_in[9];
    const float* ln2b  = (const float*)d_in[10];
    const float* w1    = (const float*)d_in[11];
    const float* b1    = (const float*)d_in[12];
    const float* w2    = (const float*)d_in[13];
    const float* b2    = (const float*)d_in[14];
    float* out = (float*)d_out;

    float *h, *qkv, *ctx, *x2, *h2, *mid, *wt;
    cudaGetSymbolAddress((void**)&h,   g_h);
    cudaGetSymbolAddress((void**)&qkv, g_qkv);
    cudaGetSymbolAddress((void**)&ctx, g_ctx);
    cudaGetSymbolAddress((void**)&x2,  g_x2);
    cudaGetSymbolAddress((void**)&h2,  g_h2);
    cudaGetSymbolAddress((void**)&mid, g_mid);
    cudaGetSymbolAddress((void**)&wt,  g_wt);

    cudaFuncSetAttribute(flash_kernel,
                         cudaFuncAttributeMaxDynamicSharedMemorySize, FLASH_SMEM);
    cudaFuncSetAttribute(gemm_tf32,
                         cudaFuncAttributeMaxDynamicSharedMemorySize, GSMEM);

    // weight prep: only QKV packed+rounded; wo/w1/w2 consumed raw (truncated by HMMA)
    pack_qkv<<<4096, 256>>>(wq, wk, wv, wt);

    // LN1 (rounded output)
    ln_kernel<<<BS, 256>>>(x, ln1s, ln1b, h);

    // fused QKV projection: [4096,1024] @ [1024,3072]
    gemm_tf32<<<dim3(QKVS / 256, BS / 128), 256, GSMEM>>>(
        h, wt, qkv, BS, QKVS, DD, nullptr, nullptr, 0, 1);

    // fused attention
    flash_kernel<<<dim3(SS / 128, BB * HH), 256, FLASH_SMEM>>>(qkv, amask, ctx);

    // output projection + residual (exact fp32 output)
    gemm_tf32<<<dim3(DD / 256, BS / 128), 256, GSMEM>>>(
        ctx, wo, x2, BS, DD, DD, bo, x, 0, 0);

    // LN2 + FFN
    ln_kernel<<<BS, 256>>>(x2, ln2s, ln2b, h2);
    gemm_tf32<<<dim3(DFF / 256, BS / 128), 256, GSMEM>>>(
        h2, w1, mid, BS, DFF, DD, b1, nullptr, 1, 1);
    gemm_tf32<<<dim3(DD / 256, BS / 128), 256, GSMEM>>>(
        mid, w2, out, BS, DD, DFF, b2, x2, 0, 0);
}

// round 9
// speedup vs baseline: 9.6100x; 1.0547x over previous
#include <cuda_runtime.h>
#include <math.h>
#include <stdint.h>

#define BB 4
#define SS 1024
#define DD 1024
#define HH 16
#define HD 64
#define BS (BB*SS)     /* 4096 */
#define DFF (4*DD)     /* 4096 */
#define QKVS 3072

// ---------------- scratch (static __device__, no allocations) ----------------
__device__ float g_h  [BS*DD];
__device__ float g_qkv[BS*QKVS];
__device__ float g_ctx[BS*DD];
__device__ float g_x2 [BS*DD];
__device__ float g_h2 [BS*DD];
__device__ float g_mid[BS*DFF];
__device__ float g_wt [12*1024*1024];  // packed qkv weights [1024][3072]

// ---------------- helpers ----------------
__device__ __forceinline__ void cpa16(void* d, const void* s) {
    asm volatile("cp.async.cg.shared.global [%0], [%1], 16;\n"
                 :: "r"((uint32_t)__cvta_generic_to_shared(d)), "l"(s));
}
__device__ __forceinline__ void cp_commit() { asm volatile("cp.async.commit_group;\n"); }
__device__ __forceinline__ void cp_wait0()  { asm volatile("cp.async.wait_group 0;\n"); }
__device__ __forceinline__ void cp_wait1()  { asm volatile("cp.async.wait_group 1;\n"); }

__device__ __forceinline__ uint32_t fu(float x) { return __float_as_uint(x); }

__device__ __forceinline__ float rna_f(float x) {
    uint32_t u;
    asm("cvt.rna.tf32.f32 %0, %1;" : "=r"(u) : "f"(x));
    return __uint_as_float(u);
}

__device__ __forceinline__ float gelu_f(float x) {
    float t = 0.7978845608028654f * (x + 0.044715f * x * x * x);
    return 0.5f * x * (1.0f + tanhf(t));
}

__device__ __forceinline__ void mma_tf32(float* c, uint32_t a0, uint32_t a1,
                                         uint32_t a2, uint32_t a3,
                                         uint32_t b0, uint32_t b1) {
    asm volatile(
        "mma.sync.aligned.m16n8k8.row.col.f32.tf32.tf32.f32 "
        "{%0,%1,%2,%3}, {%4,%5,%6,%7}, {%8,%9}, {%0,%1,%2,%3};"
        : "+f"(c[0]), "+f"(c[1]), "+f"(c[2]), "+f"(c[3])
        : "r"(a0), "r"(a1), "r"(a2), "r"(a3), "r"(b0), "r"(b1));
}

// ---------------- weight prep: pack Q,K,V weights (rna-rounded) ----------------
__global__ void pack_qkv(const float* __restrict__ wq, const float* __restrict__ wk,
                         const float* __restrict__ wv, float* __restrict__ out)
{
    int idx = blockIdx.x * 256 + threadIdx.x;     // over 1024*1024
    int k = idx >> 10, n = idx & 1023;
    size_t o = (size_t)k * QKVS + n;
    out[o]        = rna_f(wq[idx]);
    out[o + 1024] = rna_f(wk[idx]);
    out[o + 2048] = rna_f(wv[idx]);
}

// ---------------- layernorm: one block per row, single pass, rna output ----------------
__global__ void ln_kernel(const float* __restrict__ x,
                          const float* __restrict__ scale,
                          const float* __restrict__ shift,
                          float* __restrict__ out)
{
    int row = blockIdx.x;
    int t = threadIdx.x;
    const float4 xv = ((const float4*)(x + (size_t)row * DD))[t];
    __shared__ float red[256];

    float s = xv.x + xv.y + xv.z + xv.w;
    red[t] = s; __syncthreads();
    for (int o = 128; o > 0; o >>= 1) { if (t < o) red[t] += red[t + o]; __syncthreads(); }
    float mean = red[0] * (1.0f / DD);
    __syncthreads();

    float d0 = xv.x - mean, d1 = xv.y - mean, d2 = xv.z - mean, d3 = xv.w - mean;
    red[t] = d0 * d0 + d1 * d1 + d2 * d2 + d3 * d3; __syncthreads();
    for (int o = 128; o > 0; o >>= 1) { if (t < o) red[t] += red[t + o]; __syncthreads(); }
    float rstd = rsqrtf(red[0] * (1.0f / DD) + 1e-5f);

    float4 sc = ((const float4*)scale)[t];
    float4 sh = ((const float4*)shift)[t];
    ((float4*)(out + (size_t)row * DD))[t] = make_float4(
        rna_f(sc.x * d0 * rstd + sh.x), rna_f(sc.y * d1 * rstd + sh.y),
        rna_f(sc.z * d2 * rstd + sh.z), rna_f(sc.w * d3 * rstd + sh.w));
}

// ---------------- tf32 GEMM v6: 128 thr, 128x128 CTA, 64x64 warps, 3-stage ------
// C[M,N] = A[M,K] @ B[K,N] (+bias) (gelu?) (+res) (rna?); M,N mult 128, K mult 16.
#define ASZ (128*20)
#define BSZ (16*136)
#define STG (ASZ+BSZ)
#define GSMEM (3*STG*4)

__global__ __launch_bounds__(128)
void gemm_tf32(const float* __restrict__ A, const float* __restrict__ Bm,
               float* __restrict__ C, int M, int N, int K,
               const float* __restrict__ bias,
               const float* __restrict__ res,
               int gelu, int rnd)
{
    extern __shared__ float sm[];
    const int tid  = threadIdx.x;
    const int lane = tid & 31;
    const int warp = tid >> 5;           // 0..3
    const int g    = lane >> 2;
    const int tig  = lane & 3;
    const int mw   = (warp >> 1) * 64;   // 0 or 64
    const int nw   = (warp & 1) * 64;    // 0 or 64
    const int bx = blockIdx.x, by = blockIdx.y;

    const float* Ab = A + (size_t)(by * 128) * K;
    const float* Bb = Bm + (size_t)(bx * 128);

    float acc[4][8][4];
    #pragma unroll
    for (int i = 0; i < 4; i++)
        #pragma unroll
        for (int j = 0; j < 8; j++)
            #pragma unroll
            for (int c = 0; c < 4; c++) acc[i][j][c] = 0.f;

    const int T = K / 16;

#define ISSUE(sidx, k0) do {                                                    \
        float* As_ = sm + (sidx) * STG;                                         \
        float* Bs_ = sm + (sidx) * STG + ASZ;                                   \
        _Pragma("unroll")                                                       \
        for (int i_ = 0; i_ < 4; i_++) {                                        \
            int c_ = tid + i_ * 128;                                            \
            int ar_ = c_ >> 2, ak_ = (c_ & 3) * 4;                              \
            cpa16(&As_[ar_ * 20 + ak_], Ab + (size_t)ar_ * K + (k0) + ak_);     \
            int br_ = c_ >> 5, bn_ = (c_ & 31) * 4;                             \
            cpa16(&Bs_[br_ * 136 + bn_], Bb + (size_t)((k0) + br_) * N + bn_);  \
        }                                                                       \
        cp_commit();                                                            \
    } while (0)

    ISSUE(0, 0);
    ISSUE(1, 16);

    int st = 0;
    for (int t = 0; t < T; t++) {
        if (t + 2 < T) cp_wait1(); else cp_wait0();
        __syncthreads();
        if (t + 2 < T) {
            int sn = st + 2; if (sn >= 3) sn -= 3;
            ISSUE(sn, (t + 2) * 16);
        }
        const float* As = sm + st * STG;
        const float* Bs = sm + st * STG + ASZ;
        #pragma unroll
        for (int kb = 0; kb < 16; kb += 8) {
            uint32_t a[4][4], b[8][2];
            #pragma unroll
            for (int i = 0; i < 4; i++) {
                int m = mw + i * 16 + g;
                a[i][0] = fu(As[m * 20 + kb + tig]);
                a[i][1] = fu(As[(m + 8) * 20 + kb + tig]);
                a[i][2] = fu(As[m * 20 + kb + tig + 4]);
                a[i][3] = fu(As[(m + 8) * 20 + kb + tig + 4]);
            }
            #pragma unroll
            for (int j = 0; j < 8; j++) {
                int n = nw + j * 8 + g;
                b[j][0] = fu(Bs[(kb + tig) * 136 + n]);
                b[j][1] = fu(Bs[(kb + tig + 4) * 136 + n]);
            }
            #pragma unroll
            for (int i = 0; i < 4; i++)
                #pragma unroll
                for (int j = 0; j < 8; j++)
                    mma_tf32(acc[i][j], a[i][0], a[i][1], a[i][2], a[i][3],
                             b[j][0], b[j][1]);
        }
        st++; if (st >= 3) st -= 3;
    }
#undef ISSUE

    #pragma unroll
    for (int i = 0; i < 4; i++) {
        int row = by * 128 + mw + i * 16 + g;
        #pragma unroll
        for (int j = 0; j < 8; j++) {
            int col = bx * 128 + nw + j * 8 + tig * 2;
            float v0 = acc[i][j][0], v1 = acc[i][j][1];
            float v2 = acc[i][j][2], v3 = acc[i][j][3];
            if (bias) {
                float b0 = bias[col], b1 = bias[col + 1];
                v0 += b0; v1 += b1; v2 += b0; v3 += b1;
            }
            if (gelu) { v0 = gelu_f(v0); v1 = gelu_f(v1); v2 = gelu_f(v2); v3 = gelu_f(v3); }
            size_t o0 = (size_t)row * N + col;
            size_t o1 = (size_t)(row + 8) * N + col;
            if (res) {
                v0 += res[o0]; v1 += res[o0 + 1];
                v2 += res[o1]; v3 += res[o1 + 1];
            }
            if (rnd) {
                v0 = rna_f(v0); v1 = rna_f(v1); v2 = rna_f(v2); v3 = rna_f(v3);
            }
            C[o0] = v0; C[o0 + 1] = v1;
            C[o1] = v2; C[o1 + 1] = v3;
        }
    }
}

// ---------------- fused flash attention v2 (P via register shuffles) ----------------
// Reads Q,K,V from packed qkv [BS][3072]. smem 102.5 KiB -> 2 CTAs/SM.
#define FLASH_SMEM ((128*68 + 2*64*68 + 2*64*68 + 2*64) * 4)

__global__ __launch_bounds__(256, 2)
void flash_kernel(const float* __restrict__ qkv, const int* __restrict__ amask,
                  float* __restrict__ ctx)
{
    extern __shared__ float fsm[];
    float* Qs = fsm;                     // [128][68]
    float* Ks = Qs + 128 * 68;           // [2][64][68]
    float* Vs = Ks + 2 * 64 * 68;        // [2][64][68]
    float* mk = Vs + 2 * 64 * 68;        // [2][64]

    const int tid = threadIdx.x, w = tid >> 5, lane = tid & 31;
    const int g = lane >> 2, tig = lane & 3;
    const int bh = blockIdx.y, b = bh >> 4, h = bh & 15;
    const int row0 = (gridDim.x - 1 - blockIdx.x) * 128;   // heavy tiles first
    const int ntiles = row0 / 64 + 2;

    const float* qb = qkv + (size_t)(b * SS + row0) * QKVS + h * 64;
    const float* kb = qkv + (size_t)(b * SS) * QKVS + 1024 + h * 64;
    const float* vb = qkv + (size_t)(b * SS) * QKVS + 2048 + h * 64;

    #pragma unroll
    for (int i = 0; i < 8; i++) {
        int c = tid + i * 256; int r = c >> 4, dc = (c & 15) * 4;
        cpa16(&Qs[r * 68 + dc], qb + (size_t)r * QKVS + dc);
    }
    #pragma unroll
    for (int i = 0; i < 4; i++) {
        int c = tid + i * 256; int r = c >> 4, dc = (c & 15) * 4;
        cpa16(&Ks[r * 68 + dc], kb + (size_t)r * QKVS + dc);
        cpa16(&Vs[r * 68 + dc], vb + (size_t)r * QKVS + dc);
    }
    if (tid < 64) mk[tid] = amask[b * SS + tid] ? 0.f : -1e30f;
    cp_commit();

    float m0 = -1e30f, m1 = -1e30f, l0s = 0.f, l1s = 0.f;
    float acc_o[8][4];
    #pragma unroll
    for (int nt = 0; nt < 8; nt++)
        #pragma unroll
        for (int c = 0; c < 4; c++) acc_o[nt][c] = 0.f;

    const int mrow = w * 16 + g;
    const int grow0 = row0 + mrow, grow1 = grow0 + 8;
    const int srcl0 = (lane & 0x1c) | (tig >> 1);   // g*4 + tig/2
    const int srcl2 = srcl0 + 2;
    const bool codd = (tig & 1) != 0;

    for (int t = 0; t < ntiles; t++) {
        const int st = t & 1;
        cp_wait0();
        __syncthreads();
        if (t + 1 < ntiles) {
            int j0n = (t + 1) * 64, sn = st ^ 1;
            const float* kn = kb + (size_t)j0n * QKVS;
            const float* vn = vb + (size_t)j0n * QKVS;
            #pragma unroll
            for (int i = 0; i < 4; i++) {
                int c = tid + i * 256; int r = c >> 4, dc = (c & 15) * 4;
                cpa16(&Ks[(sn * 64 + r) * 68 + dc], kn + (size_t)r * QKVS + dc);
                cpa16(&Vs[(sn * 64 + r) * 68 + dc], vn + (size_t)r * QKVS + dc);
            }
            if (tid < 64) mk[sn * 64 + tid] = amask[b * SS + j0n + tid] ? 0.f : -1e30f;
            cp_commit();
        }
        const int j0 = t * 64;
        const float* Ksb = Ks + st * 64 * 68;
        const float* Vsb = Vs + st * 64 * 68;
        const float* mkb = mk + st * 64;

        // ---- S = Q K^T ----
        float accs[8][4];
        #pragma unroll
        for (int nt = 0; nt < 8; nt++)
            #pragma unroll
            for (int c = 0; c < 4; c++) accs[nt][c] = 0.f;
        #pragma unroll
        for (int ks = 0; ks < 8; ks++) {
            uint32_t a0 = fu(Qs[mrow * 68 + ks * 8 + tig]);
            uint32_t a1 = fu(Qs[(mrow + 8) * 68 + ks * 8 + tig]);
            uint32_t a2 = fu(Qs[mrow * 68 + ks * 8 + tig + 4]);
            uint32_t a3 = fu(Qs[(mrow + 8) * 68 + ks * 8 + tig + 4]);
            #pragma unroll
            for (int nt = 0; nt < 8; nt++) {
                uint32_t b0 = fu(Ksb[(g + nt * 8) * 68 + ks * 8 + tig]);
                uint32_t b1 = fu(Ksb[(g + nt * 8) * 68 + ks * 8 + tig + 4]);
                mma_tf32(accs[nt], a0, a1, a2, a3, b0, b1);
            }
        }

        // ---- mask + scale + rowmax ----
        float rm0 = -1e30f, rm1 = -1e30f;
        #pragma unroll
        for (int nt = 0; nt < 8; nt++) {
            int c0 = j0 + nt * 8 + tig * 2;
            float ma = mkb[nt * 8 + tig * 2], mb = mkb[nt * 8 + tig * 2 + 1];
            float s0 = accs[nt][0] * 0.125f + ma;
            float s1 = accs[nt][1] * 0.125f + mb;
            float s2 = accs[nt][2] * 0.125f + ma;
            float s3 = accs[nt][3] * 0.125f + mb;
            if (c0 > grow0)     s0 = -1e30f;
            if (c0 + 1 > grow0) s1 = -1e30f;
            if (c0 > grow1)     s2 = -1e30f;
            if (c0 + 1 > grow1) s3 = -1e30f;
            accs[nt][0] = s0; accs[nt][1] = s1; accs[nt][2] = s2; accs[nt][3] = s3;
            rm0 = fmaxf(rm0, fmaxf(s0, s1));
            rm1 = fmaxf(rm1, fmaxf(s2, s3));
        }
        rm0 = fmaxf(rm0, __shfl_xor_sync(0xffffffffu, rm0, 1));
        rm0 = fmaxf(rm0, __shfl_xor_sync(0xffffffffu, rm0, 2));
        rm1 = fmaxf(rm1, __shfl_xor_sync(0xffffffffu, rm1, 1));
        rm1 = fmaxf(rm1, __shfl_xor_sync(0xffffffffu, rm1, 2));

        float mn0 = fmaxf(m0, rm0), mn1 = fmaxf(m1, rm1);
        float corr0 = __expf(m0 - mn0), corr1 = __expf(m1 - mn1);
        m0 = mn0; m1 = mn1;

        // ---- P = exp(S - m) (kept in accs registers), row sums ----
        float sum0 = 0.f, sum1 = 0.f;
        #pragma unroll
        for (int nt = 0; nt < 8; nt++) {
            float p0 = __expf(accs[nt][0] - m0);
            float p1 = __expf(accs[nt][1] - m0);
            float p2 = __expf(accs[nt][2] - m1);
            float p3 = __expf(accs[nt][3] - m1);
            sum0 += p0 + p1; sum1 += p2 + p3;
            accs[nt][0] = p0; accs[nt][1] = p1; accs[nt][2] = p2; accs[nt][3] = p3;
        }
        sum0 += __shfl_xor_sync(0xffffffffu, sum0, 1);
        sum0 += __shfl_xor_sync(0xffffffffu, sum0, 2);
        sum1 += __shfl_xor_sync(0xffffffffu, sum1, 1);
        sum1 += __shfl_xor_sync(0xffffffffu, sum1, 2);
        l0s = l0s * corr0 + sum0;
        l1s = l1s * corr1 + sum1;
        #pragma unroll
        for (int nt = 0; nt < 8; nt++) {
            acc_o[nt][0] *= corr0; acc_o[nt][1] *= corr0;
            acc_o[nt][2] *= corr1; acc_o[nt][3] *= corr1;
        }

        // ---- O += P V; P A-fragments built by intra-quad shuffles ----
        // a-frag value at (row, col): col=tig (a0/a1), col=tig+4 (a2/a3);
        // accumulator holds col pairs 2c,2c+1 at quad-lane c -> shuffle+select.
        #pragma unroll
        for (int ks = 0; ks < 8; ks++) {
            float q00 = __shfl_sync(0xffffffffu, accs[ks][0], srcl0);
            float q10 = __shfl_sync(0xffffffffu, accs[ks][1], srcl0);
            float q20 = __shfl_sync(0xffffffffu, accs[ks][2], srcl0);
            float q30 = __shfl_sync(0xffffffffu, accs[ks][3], srcl0);
            float q01 = __shfl_sync(0xffffffffu, accs[ks][0], srcl2);
            float q11 = __shfl_sync(0xffffffffu, accs[ks][1], srcl2);
            float q21 = __shfl_sync(0xffffffffu, accs[ks][2], srcl2);
            float q31 = __shfl_sync(0xffffffffu, accs[ks][3], srcl2);
            uint32_t a0 = fu(codd ? q10 : q00);
            uint32_t a1 = fu(codd ? q30 : q20);
            uint32_t a2 = fu(codd ? q11 : q01);
            uint32_t a3 = fu(codd ? q31 : q21);
            #pragma unroll
            for (int nt = 0; nt < 8; nt++) {
                uint32_t b0 = fu(Vsb[(ks * 8 + tig) * 68 + nt * 8 + g]);
                uint32_t b1 = fu(Vsb[(ks * 8 + tig + 4) * 68 + nt * 8 + g]);
                mma_tf32(acc_o[nt], a0, a1, a2, a3, b0, b1);
            }
        }
    }

    float i0 = 1.f / l0s, i1 = 1.f / l1s;
    size_t base0 = (size_t)(b * SS + grow0) * DD + h * 64;
    size_t base1 = (size_t)(b * SS + grow1) * DD + h * 64;
    #pragma unroll
    for (int nt = 0; nt < 8; nt++) {
        int col = nt * 8 + tig * 2;
        *(float2*)&ctx[base0 + col] = make_float2(rna_f(acc_o[nt][0] * i0),
                                                  rna_f(acc_o[nt][1] * i0));
        *(float2*)&ctx[base1 + col] = make_float2(rna_f(acc_o[nt][2] * i1),
                                                  rna_f(acc_o[nt][3] * i1));
    }
}

// ---------------- host launch ----------------
extern "C" void kernel_launch(void* const* d_in, const int* in_sizes, int n_in,
                              void* d_out, int out_size)
{
    const float* x     = (const float*)d_in[0];
    const int*   amask = (const int*)  d_in[1];
    const float* wq    = (const float*)d_in[2];
    const float* wk    = (const float*)d_in[3];
    const float* wv    = (const float*)d_in[4];
    const float* wo    = (const float*)d_in[5];
    const float* bo    = (const float*)d_in[6];
    const float* ln1s  = (const float*)d_in[7];
    const float* ln1b  = (const float*)d_in[8];
    const float* ln2s  = (const float*)d_in[9];
    const float* ln2b  = (const float*)d_in[10];
    const float* w1    = (const float*)d_in[11];
    const float* b1    = (const float*)d_in[12];
    const float* w2    = (const float*)d_in[13];
    const float* b2    = (const float*)d_in[14];
    float* out = (float*)d_out;

    float *h, *qkv, *ctx, *x2, *h2, *mid, *wt;
    cudaGetSymbolAddress((void**)&h,   g_h);
    cudaGetSymbolAddress((void**)&qkv, g_qkv);
    cudaGetSymbolAddress((void**)&ctx, g_ctx);
    cudaGetSymbolAddress((void**)&x2,  g_x2);
    cudaGetSymbolAddress((void**)&h2,  g_h2);
    cudaGetSymbolAddress((void**)&mid, g_mid);
    cudaGetSymbolAddress((void**)&wt,  g_wt);

    cudaFuncSetAttribute(flash_kernel,
                         cudaFuncAttributeMaxDynamicSharedMemorySize, FLASH_SMEM);
    cudaFuncSetAttribute(gemm_tf32,
                         cudaFuncAttributeMaxDynamicSharedMemorySize, GSMEM);

    // weight prep: only QKV packed+rounded; wo/w1/w2 consumed raw (truncated by HMMA)
    pack_qkv<<<4096, 256>>>(wq, wk, wv, wt);

    // LN1 (rounded output)
    ln_kernel<<<BS, 256>>>(x, ln1s, ln1b, h);

    // fused QKV projection: [4096,1024] @ [1024,3072]
    gemm_tf32<<<dim3(QKVS / 128, BS / 128), 128, GSMEM>>>(
        h, wt, qkv, BS, QKVS, DD, nullptr, nullptr, 0, 1);

    // fused attention
    flash_kernel<<<dim3(SS / 128, BB * HH), 256, FLASH_SMEM>>>(qkv, amask, ctx);

    // output projection + residual (exact fp32 output)
    gemm_tf32<<<dim3(DD / 128, BS / 128), 128, GSMEM>>>(
        ctx, wo, x2, BS, DD, DD, bo, x, 0, 0);

    // LN2 + FFN
    ln_kernel<<<BS, 256>>>(x2, ln2s, ln2b, h2);
    gemm_tf32<<<dim3(DFF / 128, BS / 128), 128, GSMEM>>>(
        h2, w1, mid, BS, DFF, DD, b1, nullptr, 1, 1);
    gemm_tf32<<<dim3(DD / 128, BS / 128), 128, GSMEM>>>(
        mid, w2, out, BS, DD, DFF, b2, x2, 0, 0);
}